// round 11
// baseline (speedup 1.0000x reference)
#include <cuda_runtime.h>
#include <cuda_fp16.h>
#include <math.h>
#include <stdint.h>

// ---------------- problem constants ----------------
#define B    64
#define NF   196
#define ENC  2048
#define DEC  512
#define ATT  512
#define VOC  30000
#define EMB  512
#define TSTEPS 24
#define KCAT (EMB + ENC + DEC)   // 3072
#define GATES4 (4*DEC)           // 2048

#define ALPHA_OFF ((size_t)B * TSTEPS * VOC)

// ---------------- scratch layout (float-sized slots) ----------------
#define OFF_UHSH   ((size_t)0)                                  // B*NF*ATT/2
#define OFF_WCATP  (OFF_UHSH  + (size_t)B*NF*ATT/2)
#define OFF_FCNP   (OFF_WCATP + (size_t)(KCAT/2)*GATES4)
#define OFF_WWP    (OFF_FCNP  + (size_t)(DEC/2)*VOC)
#define OFF_IHICP  (OFF_WWP   + (size_t)(DEC/2)*ATT)            // (ENC/2)*1024
#define OFF_UWP    (OFF_IHICP + (size_t)(ENC/2)*1024)
#define OFF_FEATH  (OFF_UWP   + (size_t)(ENC/2)*ATT)
#define OFF_MEANFH (OFF_FEATH + (size_t)B*NF*ENC/2)
#define OFF_CB     (OFF_MEANFH+ (size_t)B*ENC/2)
#define OFF_HRH0   (OFF_CB    + (size_t)B*DEC)
#define OFF_HRH1   (OFF_HRH0  + (size_t)B*DEC/2)
#define OFF_WAH    (OFF_HRH1  + (size_t)B*DEC/2)
#define OFF_INCATH (OFF_WAH   + (size_t)B*ATT)
#define OFF_GATES  (OFF_INCATH+ (size_t)B*KCAT/2)
#define OFF_BCAT   (OFF_GATES + (size_t)B*GATES4)
#define OFF_SC     (OFF_BCAT  + (size_t)GATES4)
#define SCRATCH_TOTAL (OFF_SC + (size_t)B*NF)

__device__ __align__(16) float g_scratch[SCRATCH_TOTAL];

__device__ __forceinline__ float sigmoidf_(float x) {
    return 1.0f / (1.0f + expf(-x));
}
__device__ __forceinline__ float htanh(float x) {
    float y;
    asm("tanh.approx.f32 %0, %1;" : "=f"(y) : "f"(x));
    return y;
}
__device__ __forceinline__ uint32_t h2u(__half2 v) {
    return *reinterpret_cast<uint32_t*>(&v);
}
__device__ __forceinline__ float2 u2f2(uint32_t u) {
    return __half22float2(*reinterpret_cast<__half2*>(&u));
}

// ---------------- megapack: ALL weight packs in one kernel ----------------
// Each block (256 thr) writes 256 consecutive u32 of one packed row.
// Segments (block ranges, compile-time):
#define MP_UW_END    2048                      // Uw: 1024 rows x 2 chunks
#define MP_IHIC_END  (MP_UW_END + 4096)        // ih|ic: 1024 rows x 4 chunks (N=1024)
#define MP_WW_END    (MP_IHIC_END + 512)       // Ww: 256 rows x 2
#define MP_FCN_CPR   118
#define MP_FCN_END   (MP_WW_END + 256*MP_FCN_CPR)   // fcn: 256 rows x 118
#define MP_WCAT_END  (MP_FCN_END + 1536*8)     // Wcat: 1536 rows x 8
#define MP_TOTAL     (MP_WCAT_END + 8)         // bcat: 8 blocks
__global__ void __launch_bounds__(256)
megapack_kernel(const float* __restrict__ Uw,
                const float* __restrict__ ih_w,
                const float* __restrict__ ic_w,
                const float* __restrict__ Ww,
                const float* __restrict__ fcn_w,
                const float* __restrict__ W_ih,
                const float* __restrict__ W_hh,
                const float* __restrict__ b_ih,
                const float* __restrict__ b_hh,
                uint32_t* __restrict__ UwP,
                uint32_t* __restrict__ ihicP,
                uint32_t* __restrict__ WwP,
                uint32_t* __restrict__ FcnP,
                uint32_t* __restrict__ WcatP,
                float* __restrict__ bcat) {
    const int bx = blockIdx.x;
    const int tid = threadIdx.x;
    if (bx < MP_UW_END) {
        int kp = bx >> 1;
        int n = ((bx & 1) << 8) + tid;
        UwP[kp * ATT + n] = h2u(__floats2half2_rn(
            Uw[(size_t)(2 * kp) * ATT + n], Uw[(size_t)(2 * kp + 1) * ATT + n]));
    } else if (bx < MP_IHIC_END) {
        int rel = bx - MP_UW_END;
        int kp = rel >> 2;
        int n = ((rel & 3) << 8) + tid;        // 0..1023
        const float* src = (n < DEC) ? ih_w : ic_w;
        int ns = n & (DEC - 1);
        ihicP[kp * 1024 + n] = h2u(__floats2half2_rn(
            src[(size_t)(2 * kp) * DEC + ns], src[(size_t)(2 * kp + 1) * DEC + ns]));
    } else if (bx < MP_WW_END) {
        int rel = bx - MP_IHIC_END;
        int kp = rel >> 1;
        int n = ((rel & 1) << 8) + tid;
        WwP[kp * ATT + n] = h2u(__floats2half2_rn(
            Ww[(size_t)(2 * kp) * ATT + n], Ww[(size_t)(2 * kp + 1) * ATT + n]));
    } else if (bx < MP_FCN_END) {
        int rel = bx - MP_WW_END;
        int kp = rel / MP_FCN_CPR;             // div by constant
        int ch = rel - kp * MP_FCN_CPR;
        int n = ch * 256 + tid;
        if (n < VOC)
            FcnP[(size_t)kp * VOC + n] = h2u(__floats2half2_rn(
                fcn_w[(size_t)(2 * kp) * VOC + n],
                fcn_w[(size_t)(2 * kp + 1) * VOC + n]));
    } else if (bx < MP_WCAT_END) {
        int rel = bx - MP_FCN_END;
        int kp = rel >> 3;
        int n = ((rel & 7) << 8) + tid;
        int r0 = 2 * kp, r1 = 2 * kp + 1;      // split at 2560 is even -> no mixed pair
        float v0 = (r0 < EMB + ENC) ? W_ih[(size_t)r0 * GATES4 + n]
                                    : W_hh[(size_t)(r0 - EMB - ENC) * GATES4 + n];
        float v1 = (r1 < EMB + ENC) ? W_ih[(size_t)r1 * GATES4 + n]
                                    : W_hh[(size_t)(r1 - EMB - ENC) * GATES4 + n];
        WcatP[(size_t)kp * GATES4 + n] = h2u(__floats2half2_rn(v0, v1));
    } else {
        int idx = (bx - MP_WCAT_END) * 256 + tid;
        bcat[idx] = b_ih[idx] + b_hh[idx];
    }
}

// ---------------- feat2h + meanf fused (meanf reads fp32 source) ----------
#define F2H_BLOCKS (B * NF * ENC / 4 / 256)    // 25088
__global__ void __launch_bounds__(256)
feat2h_meanf_kernel(const float* __restrict__ features,
                    __half* __restrict__ featH,
                    __half* __restrict__ meanfH) {
    const int bx = blockIdx.x;
    const int tid = threadIdx.x;
    if (bx < F2H_BLOCKS) {
        int i = bx * 256 + tid;
        float4 v = reinterpret_cast<const float4*>(features)[i];
        uint2 o;
        o.x = h2u(__floats2half2_rn(v.x, v.y));
        o.y = h2u(__floats2half2_rn(v.z, v.w));
        reinterpret_cast<uint2*>(featH)[i] = o;
    } else {
        int idx = (bx - F2H_BLOCKS) * 256 + tid;   // < B*ENC/4
        int b = idx >> 9;
        int e4 = (idx & 511) * 4;
        const float* p = features + (size_t)b * NF * ENC + e4;
        float s0 = 0.f, s1 = 0.f, s2 = 0.f, s3 = 0.f;
        #pragma unroll 4
        for (int f = 0; f < NF; ++f) {
            float4 v = *reinterpret_cast<const float4*>(p + (size_t)f * ENC);
            s0 += v.x; s1 += v.y; s2 += v.z; s3 += v.w;
        }
        const float inv = 1.0f / (float)NF;
        uint2 o;
        o.x = h2u(__floats2half2_rn(s0 * inv, s1 * inv));
        o.y = h2u(__floats2half2_rn(s2 * inv, s3 * inv));
        *reinterpret_cast<uint2*>(meanfH + (size_t)b * ENC + e4) = o;
    }
}

// ---------------- fp16 tensor-core GEMM ----------------
// A row-major fp16 (lda halves); Bp k-pair packed u32 [K/2][ldb].
// MODE 0: atomicAdd fp32 C (K-split via gridDim.z)
// MODE 1: C = acc + bias (fp32)
// MODE 3: Ch = half(acc + bias)
// MODE 5: col<DEC -> Ch=half(acc+bias[col]); else C[.,col-DEC]=acc+bias2[col-DEC]
template <int MODE>
__global__ void __launch_bounds__(256)
h16_gemm(const __half* __restrict__ A, int lda,
         const uint32_t* __restrict__ Bp, int ldb,
         float* __restrict__ C, int ldc,
         const float* __restrict__ bias,
         const float* __restrict__ bias2,
         __half* __restrict__ Ch, int ldch,
         int M, int N, int K) {
    __shared__ __align__(16) uint32_t Af[1024];
    __shared__ __align__(16) uint32_t Bs[2][16][136];

    const int tid  = threadIdx.x;
    const int lane = tid & 31;
    const int warp = tid >> 5;
    const int wm = warp >> 2;
    const int wn = warp & 3;
    const int g = lane >> 2;
    const int t = lane & 3;

    const int m0 = blockIdx.y * 64;
    const int n0 = blockIdx.x * 128;
    const int chunks = (K / 32) / gridDim.z;
    const int kc0 = blockIdx.z * chunks;

    const int r = tid >> 2;
    const int cseg = tid & 3;
    const int amt = r >> 4;
    const int aks = cseg >> 1;
    const int ae = ((r >> 3) & 1) + ((cseg & 1) << 1);
    const int ag = r & 7;
    const int abase = ((((amt * 2 + aks) << 5) + (ag << 2)) << 2) + ae;

    float acc[2][4][4];
    #pragma unroll
    for (int mi = 0; mi < 2; ++mi)
        #pragma unroll
        for (int ni = 0; ni < 4; ++ni)
            #pragma unroll
            for (int q = 0; q < 4; ++q) acc[mi][ni][q] = 0.f;

    uint4 areg;
    {
        const int k0 = kc0 * 32;
        areg = *reinterpret_cast<const uint4*>(A + (size_t)(m0 + r) * lda + k0 + cseg * 8);
        const int kp0 = kc0 * 16;
        #pragma unroll
        for (int i = 0; i < 2; ++i) {
            int j = tid + i * 256;
            int br = j >> 5;
            int bc = (j & 31) * 4;
            int col = n0 + bc;
            const uint32_t* src = Bp + (size_t)(kp0 + br) * ldb + (col < N ? col : 0);
            uint32_t saddr = (uint32_t)__cvta_generic_to_shared(&Bs[0][br][bc]);
            int sz = (col < N) ? 16 : 0;
            asm volatile("cp.async.cg.shared.global [%0], [%1], 16, %2;\n"
                         :: "r"(saddr), "l"(src), "r"(sz));
        }
        asm volatile("cp.async.commit_group;\n");
        Af[abase + 0]  = areg.x;
        Af[abase + 4]  = areg.y;
        Af[abase + 8]  = areg.z;
        Af[abase + 12] = areg.w;
    }

    for (int cc = 0; cc < chunks; ++cc) {
        const int st = cc & 1;
        if (cc + 1 < chunks) {
            const int k0 = (kc0 + cc + 1) * 32;
            const int kp0 = (kc0 + cc + 1) * 16;
            #pragma unroll
            for (int i = 0; i < 2; ++i) {
                int j = tid + i * 256;
                int br = j >> 5;
                int bc = (j & 31) * 4;
                int col = n0 + bc;
                const uint32_t* src = Bp + (size_t)(kp0 + br) * ldb + (col < N ? col : 0);
                uint32_t saddr = (uint32_t)__cvta_generic_to_shared(&Bs[st ^ 1][br][bc]);
                int sz = (col < N) ? 16 : 0;
                asm volatile("cp.async.cg.shared.global [%0], [%1], 16, %2;\n"
                             :: "r"(saddr), "l"(src), "r"(sz));
            }
            areg = *reinterpret_cast<const uint4*>(A + (size_t)(m0 + r) * lda + k0 + cseg * 8);
        }
        asm volatile("cp.async.commit_group;\n");
        asm volatile("cp.async.wait_group 1;\n");
        __syncthreads();

        #pragma unroll
        for (int ks = 0; ks < 2; ++ks) {
            uint32_t af[2][4];
            #pragma unroll
            for (int mi = 0; mi < 2; ++mi) {
                int mt = wm * 2 + mi;
                uint4 a = *reinterpret_cast<const uint4*>(
                    &Af[(((mt * 2 + ks) << 5) + lane) << 2]);
                af[mi][0] = a.x; af[mi][1] = a.y; af[mi][2] = a.z; af[mi][3] = a.w;
            }
            #pragma unroll
            for (int ni = 0; ni < 4; ++ni) {
                int cB = wn * 32 + ni * 8 + g;
                uint32_t b0 = Bs[st][ks * 8 + t][cB];
                uint32_t b1 = Bs[st][ks * 8 + t + 4][cB];
                #pragma unroll
                for (int mi = 0; mi < 2; ++mi) {
                    asm volatile(
                        "mma.sync.aligned.m16n8k16.row.col.f32.f16.f16.f32 "
                        "{%0,%1,%2,%3}, {%4,%5,%6,%7}, {%8,%9}, {%0,%1,%2,%3};"
                        : "+f"(acc[mi][ni][0]), "+f"(acc[mi][ni][1]),
                          "+f"(acc[mi][ni][2]), "+f"(acc[mi][ni][3])
                        : "r"(af[mi][0]), "r"(af[mi][1]),
                          "r"(af[mi][2]), "r"(af[mi][3]),
                          "r"(b0), "r"(b1));
                }
            }
        }
        __syncthreads();
        if (cc + 1 < chunks) {
            Af[abase + 0]  = areg.x;
            Af[abase + 4]  = areg.y;
            Af[abase + 8]  = areg.z;
            Af[abase + 12] = areg.w;
        }
    }

    #pragma unroll
    for (int mi = 0; mi < 2; ++mi) {
        int r0 = m0 + wm * 32 + mi * 16 + g;
        #pragma unroll
        for (int ni = 0; ni < 4; ++ni) {
            int col = n0 + wn * 32 + ni * 8 + 2 * t;
            if (col >= N) continue;
            if (MODE == 0) {
                atomicAdd(&C[(size_t)r0 * ldc + col],           acc[mi][ni][0]);
                atomicAdd(&C[(size_t)r0 * ldc + col + 1],       acc[mi][ni][1]);
                atomicAdd(&C[(size_t)(r0 + 8) * ldc + col],     acc[mi][ni][2]);
                atomicAdd(&C[(size_t)(r0 + 8) * ldc + col + 1], acc[mi][ni][3]);
            } else if (MODE == 1) {
                float bv0 = bias[col], bv1 = bias[col + 1];
                *reinterpret_cast<float2*>(&C[(size_t)r0 * ldc + col]) =
                    make_float2(acc[mi][ni][0] + bv0, acc[mi][ni][1] + bv1);
                *reinterpret_cast<float2*>(&C[(size_t)(r0 + 8) * ldc + col]) =
                    make_float2(acc[mi][ni][2] + bv0, acc[mi][ni][3] + bv1);
            } else if (MODE == 3) {
                float bv0 = bias[col], bv1 = bias[col + 1];
                *reinterpret_cast<__half2*>(&Ch[(size_t)r0 * ldch + col]) =
                    __floats2half2_rn(acc[mi][ni][0] + bv0, acc[mi][ni][1] + bv1);
                *reinterpret_cast<__half2*>(&Ch[(size_t)(r0 + 8) * ldch + col]) =
                    __floats2half2_rn(acc[mi][ni][2] + bv0, acc[mi][ni][3] + bv1);
            } else {  // MODE 5
                if (col < DEC) {
                    float bv0 = bias[col], bv1 = bias[col + 1];
                    *reinterpret_cast<__half2*>(&Ch[(size_t)r0 * ldch + col]) =
                        __floats2half2_rn(acc[mi][ni][0] + bv0, acc[mi][ni][1] + bv1);
                    *reinterpret_cast<__half2*>(&Ch[(size_t)(r0 + 8) * ldch + col]) =
                        __floats2half2_rn(acc[mi][ni][2] + bv0, acc[mi][ni][3] + bv1);
                } else {
                    int c2 = col - DEC;
                    float bv0 = bias2[c2], bv1 = bias2[c2 + 1];
                    *reinterpret_cast<float2*>(&C[(size_t)r0 * ldc + c2]) =
                        make_float2(acc[mi][ni][0] + bv0, acc[mi][ni][1] + bv1);
                    *reinterpret_cast<float2*>(&C[(size_t)(r0 + 8) * ldc + c2]) =
                        make_float2(acc[mi][ni][2] + bv0, acc[mi][ni][3] + bv1);
                }
            }
        }
    }
}

// ---------------- scores: grid (4, B), 256 threads ----------------
__global__ void __launch_bounds__(256)
scores_kernel(const __half* __restrict__ uhsH,
              const float* __restrict__ wah,     // includes Wb bias
              const float* __restrict__ Aw,
              const float* __restrict__ Ab,
              const int* __restrict__ captions,
              const float* __restrict__ emb,
              const float* __restrict__ bcat,
              const __half* __restrict__ hrH,
              __half* __restrict__ incatH,
              float* __restrict__ gates,
              float* __restrict__ scores,
              int t) {
    const int q = blockIdx.x;
    const int b = blockIdx.y;
    const int tid = threadIdx.x;
    const int warp = tid >> 5;
    const int lane = tid & 31;

    __shared__ __align__(16) float s_wah[ATT];
    __shared__ __align__(16) float s_Aw[ATT];

    for (int i = tid; i < ATT; i += 256) {
        s_wah[i] = wah[b * ATT + i];
        s_Aw[i]  = Aw[i];
    }
    __syncthreads();

    {
        int tok = captions[b * (TSTEPS + 1) + t];
        if (tid < 128) {
            int iq = q * 128 + tid;
            incatH[(size_t)b * KCAT + iq] = __float2half_rn(emb[(size_t)tok * EMB + iq]);
            incatH[(size_t)b * KCAT + EMB + ENC + iq] = hrH[b * DEC + iq];
        }
        int i0 = q * 512 + tid;
        gates[(size_t)b * GATES4 + i0]       = bcat[i0];
        gates[(size_t)b * GATES4 + i0 + 256] = bcat[i0 + 256];
    }

    const float Ab0 = Ab[0];
    const int f0 = q * 49;
    for (int f = f0 + warp; f < f0 + 49; f += 8) {
        const __half* u = uhsH + ((size_t)(b * NF + f)) * ATT;
        float a0 = 0.f, a1 = 0.f, a2 = 0.f, a3 = 0.f;
        #pragma unroll
        for (int kk = 0; kk < 4; ++kk) {
            int k = kk * 128 + lane * 4;
            uint2 uv = *reinterpret_cast<const uint2*>(u + k);
            float2 f01 = u2f2(uv.x);
            float2 f23 = u2f2(uv.y);
            float4 wv = *reinterpret_cast<const float4*>(&s_wah[k]);
            float4 av = *reinterpret_cast<const float4*>(&s_Aw[k]);
            a0 += htanh(f01.x + wv.x) * av.x;
            a1 += htanh(f01.y + wv.y) * av.y;
            a2 += htanh(f23.x + wv.z) * av.z;
            a3 += htanh(f23.y + wv.w) * av.w;
        }
        float acc = (a0 + a1) + (a2 + a3);
        #pragma unroll
        for (int o = 16; o; o >>= 1) acc += __shfl_xor_sync(0xffffffffu, acc, o);
        if (lane == 0) scores[b * NF + f] = acc + Ab0;
    }
}

// ---------------- ctx: softmax + context slice, grid (4, B), 512 threads ----
__global__ void __launch_bounds__(512)
ctx_kernel(const float* __restrict__ scores,
           const __half* __restrict__ featH,
           __half* __restrict__ incatH,
           float* __restrict__ alpha_out) {
    const int y = blockIdx.x;
    const int b = blockIdx.y;
    const int tid = threadIdx.x;
    const int warp = tid >> 5;
    const int lane = tid & 31;

    __shared__ float s_al[NF];
    __shared__ float s_red[16];
    __shared__ __align__(16) float4 s_part[4][128];

    float v = (tid < NF) ? scores[b * NF + tid] : -1e30f;
    float m = v;
    #pragma unroll
    for (int o = 16; o; o >>= 1) m = fmaxf(m, __shfl_xor_sync(0xffffffffu, m, o));
    if (lane == 0) s_red[warp] = m;
    __syncthreads();
    if (tid == 0) {
        float mm = s_red[0];
        #pragma unroll
        for (int w = 1; w < 16; ++w) mm = fmaxf(mm, s_red[w]);
        s_red[0] = mm;
    }
    __syncthreads();
    const float mx = s_red[0];
    __syncthreads();
    float e = (tid < NF) ? expf(v - mx) : 0.f;
    float s = e;
    #pragma unroll
    for (int o = 16; o; o >>= 1) s += __shfl_xor_sync(0xffffffffu, s, o);
    if (lane == 0) s_red[warp] = s;
    __syncthreads();
    if (tid == 0) {
        float ss = 0.f;
        #pragma unroll
        for (int w = 0; w < 16; ++w) ss += s_red[w];
        s_red[0] = ss;
    }
    __syncthreads();
    const float inv_denom = 1.0f / s_red[0];
    if (tid < NF) {
        float alpha = e * inv_denom;
        s_al[tid] = alpha;
        if (y == 0)
            alpha_out[(size_t)b * (TSTEPS * NF) + tid] = alpha;
    }
    __syncthreads();

    const int sub = tid >> 7;
    const int c4  = tid & 127;
    const int col = y * 512 + c4 * 4;
    const __half* fp = featH + (size_t)b * NF * ENC + col;
    float cx = 0.f, cy = 0.f, cz = 0.f, cw = 0.f;
    const int fs = sub * 49;
    #pragma unroll 7
    for (int f = fs; f < fs + 49; ++f) {
        uint2 fv = *reinterpret_cast<const uint2*>(fp + (size_t)f * ENC);
        float2 lo = u2f2(fv.x);
        float2 hi = u2f2(fv.y);
        float a = s_al[f];
        cx += a * lo.x; cy += a * lo.y; cz += a * hi.x; cw += a * hi.y;
    }
    s_part[sub][c4] = make_float4(cx, cy, cz, cw);
    __syncthreads();
    if (tid < 128) {
        float4 p0 = s_part[0][tid], p1 = s_part[1][tid];
        float4 p2 = s_part[2][tid], p3 = s_part[3][tid];
        uint2 o;
        o.x = h2u(__floats2half2_rn(p0.x + p1.x + p2.x + p3.x,
                                    p0.y + p1.y + p2.y + p3.y));
        o.y = h2u(__floats2half2_rn(p0.z + p1.z + p2.z + p3.z,
                                    p0.w + p1.w + p2.w + p3.w));
        *reinterpret_cast<uint2*>(
            &incatH[(size_t)b * KCAT + EMB + y * 512 + tid * 4]) = o;
    }
}

// ---------------- fused LSTM + wah GEMV: grid (B), 256 threads ----------------
// Phase 1: lstm pointwise (2 outputs/thread), h stashed (half-rounded) in smem.
// Phase 2: wah[b][n] = Wb[n] + sum_k h[k]*Ww[k][n]  (fp32 FMA, coalesced u64 loads)
__global__ void __launch_bounds__(256)
lstm_wah_kernel(const float* __restrict__ gates,
                __half* __restrict__ hrH,
                float* __restrict__ c,
                const uint32_t* __restrict__ WwP,
                const float* __restrict__ Wb,
                float* __restrict__ wah) {
    const int b = blockIdx.x;
    const int tid = threadIdx.x;
    __shared__ float s_h[DEC];

    const int n2 = tid * 2;
    {
        const float* g = gates + (size_t)b * GATES4;
        float2 gi = *reinterpret_cast<const float2*>(g + n2);
        float2 gf = *reinterpret_cast<const float2*>(g + DEC + n2);
        float2 gg = *reinterpret_cast<const float2*>(g + 2 * DEC + n2);
        float2 go = *reinterpret_cast<const float2*>(g + 3 * DEC + n2);
        float2 cc = *reinterpret_cast<const float2*>(c + (size_t)b * DEC + n2);
        float c0 = sigmoidf_(gf.x) * cc.x + sigmoidf_(gi.x) * tanhf(gg.x);
        float c1 = sigmoidf_(gf.y) * cc.y + sigmoidf_(gi.y) * tanhf(gg.y);
        float h0 = sigmoidf_(go.x) * tanhf(c0);
        float h1 = sigmoidf_(go.y) * tanhf(c1);
        __half2 hh = __floats2half2_rn(h0, h1);
        *reinterpret_cast<float2*>(c + (size_t)b * DEC + n2) = make_float2(c0, c1);
        *reinterpret_cast<__half2*>(hrH + (size_t)b * DEC + n2) = hh;
        float2 hr = __half22float2(hh);
        s_h[n2] = hr.x;
        s_h[n2 + 1] = hr.y;
    }
    __syncthreads();

    float a0 = Wb[n2], a1 = Wb[n2 + 1];
    #pragma unroll 8
    for (int kp = 0; kp < DEC / 2; ++kp) {
        uint2 wv = *reinterpret_cast<const uint2*>(WwP + (size_t)kp * ATT + n2);
        float2 hk = *reinterpret_cast<const float2*>(&s_h[2 * kp]);  // broadcast
        float2 w0 = u2f2(wv.x);   // (k=2kp, k=2kp+1) for col n2
        float2 w1 = u2f2(wv.y);   // for col n2+1
        a0 += hk.x * w0.x + hk.y * w0.y;
        a1 += hk.x * w1.x + hk.y * w1.y;
    }
    *reinterpret_cast<float2*>(&wah[(size_t)b * ATT + n2]) = make_float2(a0, a1);
}

// ---------------- launch ----------------
extern "C" void kernel_launch(void* const* d_in, const int* in_sizes, int n_in,
                              void* d_out, int out_size) {
    const float* features = (const float*)d_in[0];
    const int*   captions = (const int*)  d_in[1];
    const float* emb      = (const float*)d_in[2];
    const float* Uw       = (const float*)d_in[3];
    const float* Ub       = (const float*)d_in[4];
    const float* Ww       = (const float*)d_in[5];
    const float* Wb       = (const float*)d_in[6];
    const float* Aw       = (const float*)d_in[7];
    const float* Ab       = (const float*)d_in[8];
    const float* ih_w     = (const float*)d_in[9];
    const float* ih_b     = (const float*)d_in[10];
    const float* ic_w     = (const float*)d_in[11];
    const float* ic_b     = (const float*)d_in[12];
    const float* W_ih     = (const float*)d_in[13];
    const float* b_ih     = (const float*)d_in[14];
    const float* W_hh     = (const float*)d_in[15];
    const float* b_hh     = (const float*)d_in[16];
    const float* fcn_w    = (const float*)d_in[17];
    const float* fcn_b    = (const float*)d_in[18];
    float* out = (float*)d_out;

    float* S = nullptr;
    cudaGetSymbolAddress((void**)&S, g_scratch);
    __half*   uhsH   = reinterpret_cast<__half*>(S + OFF_UHSH);
    uint32_t* WcatP  = reinterpret_cast<uint32_t*>(S + OFF_WCATP);
    uint32_t* FcnP   = reinterpret_cast<uint32_t*>(S + OFF_FCNP);
    uint32_t* WwP    = reinterpret_cast<uint32_t*>(S + OFF_WWP);
    uint32_t* ihicP  = reinterpret_cast<uint32_t*>(S + OFF_IHICP);
    uint32_t* UwP    = reinterpret_cast<uint32_t*>(S + OFF_UWP);
    __half*   featH  = reinterpret_cast<__half*>(S + OFF_FEATH);
    __half*   meanfH = reinterpret_cast<__half*>(S + OFF_MEANFH);
    float*    c      = S + OFF_CB;
    __half*   hrH[2] = { reinterpret_cast<__half*>(S + OFF_HRH0),
                         reinterpret_cast<__half*>(S + OFF_HRH1) };
    float*    wah    = S + OFF_WAH;
    __half*   incatH = reinterpret_cast<__half*>(S + OFF_INCATH);
    float*    gates  = S + OFF_GATES;
    float*    bcat   = S + OFF_BCAT;
    float*    sc     = S + OFF_SC;

    // ONE auxiliary stream (two tripped the teardown memory-baseline check).
    cudaStream_t s2;
    cudaStreamCreateWithFlags(&s2, cudaStreamNonBlocking);
    cudaEvent_t fork_ev[2], join_ev[2], start_ev, mp_ev;
    for (int i = 0; i < 2; ++i) {
        cudaEventCreateWithFlags(&fork_ev[i], cudaEventDisableTiming);
        cudaEventCreateWithFlags(&join_ev[i], cudaEventDisableTiming);
    }
    cudaEventCreateWithFlags(&start_ev, cudaEventDisableTiming);
    cudaEventCreateWithFlags(&mp_ev, cudaEventDisableTiming);

    cudaEventRecord(start_ev, 0);
    cudaStreamWaitEvent(s2, start_ev, 0);

    // ---- prep: submission order makes uhs GEMM the 4th kernel (ncu target) ----
    // 1) main: feat2h + meanf (fused, both read fp32 features)
    feat2h_meanf_kernel<<<F2H_BLOCKS + B * ENC / 4 / 256, 256>>>(
        features, featH, meanfH);
    // 2) s2: ALL weight packs in one kernel
    megapack_kernel<<<MP_TOTAL, 256, 0, s2>>>(Uw, ih_w, ic_w, Ww, fcn_w,
                                              W_ih, W_hh, b_ih, b_hh,
                                              UwP, ihicP, WwP, FcnP, WcatP, bcat);
    cudaEventRecord(mp_ev, s2);
    cudaStreamWaitEvent(0, mp_ev, 0);
    // 3) main: [h0 | c0] = meanfH @ [ih|ic] (MODE5: fp16 h -> hrH[1], fp32 c)
    h16_gemm<5><<<dim3(1024 / 128, 1, 1), 256>>>(meanfH, ENC, ihicP, 1024,
        c, DEC, ih_b, ic_b, hrH[1], DEC, B, 1024, ENC);
    // 4) main: uhs = featH @ UwP + Ub  (12544 x 512 x 2048)  <- ncu capture
    h16_gemm<3><<<dim3(ATT / 128, (B * NF) / 64, 1), 256>>>(featH, ENC, UwP, ATT,
        nullptr, 0, Ub, nullptr, uhsH, ATT, B * NF, ATT, ENC);
    // 5) main: wah0 = h0 @ Ww + Wb
    h16_gemm<1><<<dim3(ATT / 128, 1, 1), 256>>>(hrH[1], DEC, WwP, ATT,
        wah, ATT, Wb, nullptr, nullptr, 0, B, ATT, DEC);

    // ---- recurrent steps (4 main kernels/step) ----
    for (int t = 0; t < TSTEPS; ++t) {
        float* alpha_t = out + ALPHA_OFF + (size_t)t * NF;
        __half* hr_in  = hrH[(t + 1) & 1];
        __half* hr_out = hrH[t & 1];

        scores_kernel<<<dim3(4, B), 256>>>(uhsH, wah, Aw, Ab, captions, emb,
                                           bcat, hr_in, incatH, gates, sc, t);
        ctx_kernel<<<dim3(4, B), 512>>>(sc, featH, incatH, alpha_t);
        h16_gemm<0><<<dim3(GATES4 / 128, 1, 8), 256>>>(incatH, KCAT, WcatP, GATES4,
            gates, GATES4, nullptr, nullptr, nullptr, 0, B, GATES4, KCAT);
        // preds from 2 steps ago must be done reading this hr buffer
        if (t >= 2) cudaStreamWaitEvent(0, join_ev[t & 1], 0);
        lstm_wah_kernel<<<B, 256>>>(gates, hr_out, c, WwP, Wb, wah);
        cudaEventRecord(fork_ev[t & 1], 0);
        // preds_t — off critical path on s2
        cudaStreamWaitEvent(s2, fork_ev[t & 1], 0);
        h16_gemm<1><<<dim3((VOC + 127) / 128, 1, 1), 256, 0, s2>>>(hr_out, DEC,
            FcnP, VOC, out + (size_t)t * VOC, TSTEPS * VOC, fcn_b, nullptr,
            nullptr, 0, B, VOC, DEC);
        cudaEventRecord(join_ev[t & 1], s2);
    }
    cudaStreamWaitEvent(0, join_ev[(TSTEPS - 1) & 1], 0);
    cudaStreamWaitEvent(0, join_ev[(TSTEPS - 2) & 1], 0);
}

// round 12
// speedup vs baseline: 1.3783x; 1.3783x over previous
#include <cuda_runtime.h>
#include <cuda_fp16.h>
#include <math.h>
#include <stdint.h>

// ---------------- problem constants ----------------
#define B    64
#define NF   196
#define ENC  2048
#define DEC  512
#define ATT  512
#define VOC  30000
#define EMB  512
#define TSTEPS 24
#define KCAT (EMB + ENC + DEC)   // 3072
#define GATES4 (4*DEC)           // 2048

#define ALPHA_OFF ((size_t)B * TSTEPS * VOC)

// ---------------- scratch layout (float-sized slots) ----------------
#define OFF_UHSH   ((size_t)0)
#define OFF_WCATP  (OFF_UHSH  + (size_t)B*NF*ATT/2)
#define OFF_FCNP   (OFF_WCATP + (size_t)(KCAT/2)*GATES4)
#define OFF_WWP    (OFF_FCNP  + (size_t)(DEC/2)*VOC)
#define OFF_IHP    (OFF_WWP   + (size_t)(DEC/2)*ATT)
#define OFF_ICP    (OFF_IHP   + (size_t)(ENC/2)*DEC)
#define OFF_UWP    (OFF_ICP   + (size_t)(ENC/2)*DEC)
#define OFF_FEATH  (OFF_UWP   + (size_t)(ENC/2)*ATT)
#define OFF_MEANFH (OFF_FEATH + (size_t)B*NF*ENC/2)
#define OFF_CB     (OFF_MEANFH+ (size_t)B*ENC/2)
#define OFF_HRH0   (OFF_CB    + (size_t)B*DEC)
#define OFF_HRH1   (OFF_HRH0  + (size_t)B*DEC/2)
#define OFF_WAH    (OFF_HRH1  + (size_t)B*DEC/2)
#define OFF_INCATH (OFF_WAH   + (size_t)B*ATT)
#define OFF_GATES  (OFF_INCATH+ (size_t)B*KCAT/2)
#define OFF_BCAT   (OFF_GATES + (size_t)B*GATES4)
#define OFF_SC     (OFF_BCAT  + (size_t)GATES4)
#define SCRATCH_TOTAL (OFF_SC + (size_t)B*NF)

__device__ __align__(16) float g_scratch[SCRATCH_TOTAL];

__device__ __forceinline__ float sigmoidf_(float x) {
    return 1.0f / (1.0f + expf(-x));
}
__device__ __forceinline__ float htanh(float x) {
    float y;
    asm("tanh.approx.f32 %0, %1;" : "=f"(y) : "f"(x));
    return y;
}
__device__ __forceinline__ uint32_t h2u(__half2 v) {
    return *reinterpret_cast<uint32_t*>(&v);
}
__device__ __forceinline__ float2 u2f2(uint32_t u) {
    return __half22float2(*reinterpret_cast<__half2*>(&u));
}

// ---------------- prep: pack W (K x N fp32) into k-pair half2 u32 ----------
__global__ void pack_weight_kernel(const float* __restrict__ W,
                                   uint32_t* __restrict__ P, int K, int N) {
    int total = (K / 2) * N;
    for (int i = blockIdx.x * blockDim.x + threadIdx.x; i < total;
         i += gridDim.x * blockDim.x) {
        int kp = i / N;
        int n = i - kp * N;
        P[i] = h2u(__floats2half2_rn(W[(size_t)(2 * kp) * N + n],
                                     W[(size_t)(2 * kp + 1) * N + n]));
    }
}

__global__ void prep_wcat_kernel(const float* __restrict__ W_ih,
                                 const float* __restrict__ W_hh,
                                 const float* __restrict__ b_ih,
                                 const float* __restrict__ b_hh,
                                 uint32_t* __restrict__ WcatP,
                                 float* __restrict__ bcat) {
    int total = (KCAT / 2) * GATES4;
    for (int i = blockIdx.x * blockDim.x + threadIdx.x; i < total;
         i += gridDim.x * blockDim.x) {
        int kp = i / GATES4;
        int n = i - kp * GATES4;
        int r0 = 2 * kp, r1 = 2 * kp + 1;
        float v0 = (r0 < EMB + ENC) ? W_ih[(size_t)r0 * GATES4 + n]
                                    : W_hh[(size_t)(r0 - EMB - ENC) * GATES4 + n];
        float v1 = (r1 < EMB + ENC) ? W_ih[(size_t)r1 * GATES4 + n]
                                    : W_hh[(size_t)(r1 - EMB - ENC) * GATES4 + n];
        WcatP[i] = h2u(__floats2half2_rn(v0, v1));
    }
    int idx = blockIdx.x * blockDim.x + threadIdx.x;
    if (idx < GATES4) bcat[idx] = b_ih[idx] + b_hh[idx];
}

__global__ void feat2h_kernel(const float* __restrict__ src,
                              __half* __restrict__ dst, int n4) {
    int i = blockIdx.x * blockDim.x + threadIdx.x;
    if (i < n4) {
        float4 v = reinterpret_cast<const float4*>(src)[i];
        uint2 o;
        o.x = h2u(__floats2half2_rn(v.x, v.y));
        o.y = h2u(__floats2half2_rn(v.z, v.w));
        reinterpret_cast<uint2*>(dst)[i] = o;
    }
}

__global__ void meanf_h_kernel(const __half* __restrict__ featH,
                               __half* __restrict__ meanfH) {
    int idx = blockIdx.x * blockDim.x + threadIdx.x;
    if (idx >= B * (ENC / 4)) return;
    int b = idx / (ENC / 4);
    int e4 = (idx - b * (ENC / 4)) * 4;
    const __half* p = featH + (size_t)b * NF * ENC + e4;
    float s0 = 0.f, s1 = 0.f, s2 = 0.f, s3 = 0.f;
    #pragma unroll 4
    for (int f = 0; f < NF; ++f) {
        uint2 v = *reinterpret_cast<const uint2*>(p + (size_t)f * ENC);
        float2 lo = u2f2(v.x);
        float2 hi = u2f2(v.y);
        s0 += lo.x; s1 += lo.y; s2 += hi.x; s3 += hi.y;
    }
    const float inv = 1.0f / (float)NF;
    uint2 o;
    o.x = h2u(__floats2half2_rn(s0 * inv, s1 * inv));
    o.y = h2u(__floats2half2_rn(s2 * inv, s3 * inv));
    *reinterpret_cast<uint2*>(meanfH + (size_t)b * ENC + e4) = o;
}

// ---------------- fp16 tensor-core GEMM (pipelined: 3x Bs, 2x Af, 1 barrier) --
// A row-major fp16 (lda halves); Bp k-pair packed u32 [K/2][ldb].
// MODE 0: atomicAdd fp32 C (K-split via gridDim.z)
// MODE 1: C = acc + bias (fp32)
// MODE 3: Ch = half(acc + bias)
template <int MODE>
__global__ void __launch_bounds__(256)
h16_gemm(const __half* __restrict__ A, int lda,
         const uint32_t* __restrict__ Bp, int ldb,
         float* __restrict__ C, int ldc,
         const float* __restrict__ bias,
         __half* __restrict__ Ch, int ldch,
         int M, int N, int K) {
    __shared__ __align__(16) uint32_t Af[2][1024];       // 8 KB
    __shared__ __align__(16) uint32_t Bs[3][16][136];    // 26.1 KB

    const int tid  = threadIdx.x;
    const int lane = tid & 31;
    const int warp = tid >> 5;
    const int wm = warp >> 2;
    const int wn = warp & 3;
    const int g = lane >> 2;
    const int t = lane & 3;

    const int m0 = blockIdx.y * 64;
    const int n0 = blockIdx.x * 128;
    const int chunks = (K / 32) / gridDim.z;
    const int kc0 = blockIdx.z * chunks;

    const int r = tid >> 2;
    const int cseg = tid & 3;
    const int amt = r >> 4;
    const int aks = cseg >> 1;
    const int ae = ((r >> 3) & 1) + ((cseg & 1) << 1);
    const int ag = r & 7;
    const int abase = ((((amt * 2 + aks) << 5) + (ag << 2)) << 2) + ae;

    float acc[2][4][4];
    #pragma unroll
    for (int mi = 0; mi < 2; ++mi)
        #pragma unroll
        for (int ni = 0; ni < 4; ++ni)
            #pragma unroll
            for (int q = 0; q < 4; ++q) acc[mi][ni][q] = 0.f;

    uint4 areg;
    // ---- prologue: chunk0 -> Bs[0] (cp.async) + Af[0] (regs->smem)
    {
        const int k0 = kc0 * 32;
        areg = *reinterpret_cast<const uint4*>(A + (size_t)(m0 + r) * lda + k0 + cseg * 8);
        const int kp0 = kc0 * 16;
        #pragma unroll
        for (int i = 0; i < 2; ++i) {
            int j = tid + i * 256;
            int br = j >> 5;
            int bc = (j & 31) * 4;
            int col = n0 + bc;
            const uint32_t* src = Bp + (size_t)(kp0 + br) * ldb + (col < N ? col : 0);
            uint32_t saddr = (uint32_t)__cvta_generic_to_shared(&Bs[0][br][bc]);
            int sz = (col < N) ? 16 : 0;
            asm volatile("cp.async.cg.shared.global [%0], [%1], 16, %2;\n"
                         :: "r"(saddr), "l"(src), "r"(sz));
        }
        asm volatile("cp.async.commit_group;\n");
        Af[0][abase + 0]  = areg.x;
        Af[0][abase + 4]  = areg.y;
        Af[0][abase + 8]  = areg.z;
        Af[0][abase + 12] = areg.w;
    }

    int st = 0;   // Bs buffer holding chunk cc
    for (int cc = 0; cc < chunks; ++cc) {
        int stn = st + 1; if (stn == 3) stn = 0;
        if (cc + 1 < chunks) {
            const int k0 = (kc0 + cc + 1) * 32;
            const int kp0 = (kc0 + cc + 1) * 16;
            #pragma unroll
            for (int i = 0; i < 2; ++i) {
                int j = tid + i * 256;
                int br = j >> 5;
                int bc = (j & 31) * 4;
                int col = n0 + bc;
                const uint32_t* src = Bp + (size_t)(kp0 + br) * ldb + (col < N ? col : 0);
                uint32_t saddr = (uint32_t)__cvta_generic_to_shared(&Bs[stn][br][bc]);
                int sz = (col < N) ? 16 : 0;
                asm volatile("cp.async.cg.shared.global [%0], [%1], 16, %2;\n"
                             :: "r"(saddr), "l"(src), "r"(sz));
            }
            areg = *reinterpret_cast<const uint4*>(A + (size_t)(m0 + r) * lda + k0 + cseg * 8);
        }
        asm volatile("cp.async.commit_group;\n");
        asm volatile("cp.async.wait_group 1;\n");
        __syncthreads();                       // single barrier per chunk
        if (cc + 1 < chunks) {
            uint32_t* afn = Af[(cc + 1) & 1];
            afn[abase + 0]  = areg.x;
            afn[abase + 4]  = areg.y;
            afn[abase + 8]  = areg.z;
            afn[abase + 12] = areg.w;
        }
        const uint32_t* afc = Af[cc & 1];

        #pragma unroll
        for (int ks = 0; ks < 2; ++ks) {
            uint32_t af[2][4];
            #pragma unroll
            for (int mi = 0; mi < 2; ++mi) {
                int mt = wm * 2 + mi;
                uint4 a = *reinterpret_cast<const uint4*>(
                    &afc[(((mt * 2 + ks) << 5) + lane) << 2]);
                af[mi][0] = a.x; af[mi][1] = a.y; af[mi][2] = a.z; af[mi][3] = a.w;
            }
            #pragma unroll
            for (int ni = 0; ni < 4; ++ni) {
                int cB = wn * 32 + ni * 8 + g;
                uint32_t b0 = Bs[st][ks * 8 + t][cB];
                uint32_t b1 = Bs[st][ks * 8 + t + 4][cB];
                #pragma unroll
                for (int mi = 0; mi < 2; ++mi) {
                    asm volatile(
                        "mma.sync.aligned.m16n8k16.row.col.f32.f16.f16.f32 "
                        "{%0,%1,%2,%3}, {%4,%5,%6,%7}, {%8,%9}, {%0,%1,%2,%3};"
                        : "+f"(acc[mi][ni][0]), "+f"(acc[mi][ni][1]),
                          "+f"(acc[mi][ni][2]), "+f"(acc[mi][ni][3])
                        : "r"(af[mi][0]), "r"(af[mi][1]),
                          "r"(af[mi][2]), "r"(af[mi][3]),
                          "r"(b0), "r"(b1));
                }
            }
        }
        st = stn;
    }

    #pragma unroll
    for (int mi = 0; mi < 2; ++mi) {
        int r0 = m0 + wm * 32 + mi * 16 + g;
        #pragma unroll
        for (int ni = 0; ni < 4; ++ni) {
            int col = n0 + wn * 32 + ni * 8 + 2 * t;
            if (col >= N) continue;
            if (MODE == 0) {
                atomicAdd(&C[(size_t)r0 * ldc + col],           acc[mi][ni][0]);
                atomicAdd(&C[(size_t)r0 * ldc + col + 1],       acc[mi][ni][1]);
                atomicAdd(&C[(size_t)(r0 + 8) * ldc + col],     acc[mi][ni][2]);
                atomicAdd(&C[(size_t)(r0 + 8) * ldc + col + 1], acc[mi][ni][3]);
            } else if (MODE == 1) {
                float bv0 = bias[col], bv1 = bias[col + 1];
                *reinterpret_cast<float2*>(&C[(size_t)r0 * ldc + col]) =
                    make_float2(acc[mi][ni][0] + bv0, acc[mi][ni][1] + bv1);
                *reinterpret_cast<float2*>(&C[(size_t)(r0 + 8) * ldc + col]) =
                    make_float2(acc[mi][ni][2] + bv0, acc[mi][ni][3] + bv1);
            } else {
                float bv0 = bias[col], bv1 = bias[col + 1];
                *reinterpret_cast<__half2*>(&Ch[(size_t)r0 * ldch + col]) =
                    __floats2half2_rn(acc[mi][ni][0] + bv0, acc[mi][ni][1] + bv1);
                *reinterpret_cast<__half2*>(&Ch[(size_t)(r0 + 8) * ldch + col]) =
                    __floats2half2_rn(acc[mi][ni][2] + bv0, acc[mi][ni][3] + bv1);
            }
        }
    }
}

// ---------------- scores: grid (4, B), 256 threads ----------------
__global__ void __launch_bounds__(256)
scores_kernel(const __half* __restrict__ uhsH,
              const float* __restrict__ wah,     // includes Wb bias
              const float* __restrict__ Aw,
              const float* __restrict__ Ab,
              const int* __restrict__ captions,
              const float* __restrict__ emb,
              const float* __restrict__ bcat,
              const __half* __restrict__ hrH,
              __half* __restrict__ incatH,
              float* __restrict__ gates,
              float* __restrict__ scores,
              int t) {
    const int q = blockIdx.x;
    const int b = blockIdx.y;
    const int tid = threadIdx.x;
    const int warp = tid >> 5;
    const int lane = tid & 31;

    __shared__ __align__(16) float s_wah[ATT];
    __shared__ __align__(16) float s_Aw[ATT];

    for (int i = tid; i < ATT; i += 256) {
        s_wah[i] = wah[b * ATT + i];
        s_Aw[i]  = Aw[i];
    }
    __syncthreads();

    {
        int tok = captions[b * (TSTEPS + 1) + t];
        if (tid < 128) {
            int iq = q * 128 + tid;
            incatH[(size_t)b * KCAT + iq] = __float2half_rn(emb[(size_t)tok * EMB + iq]);
            incatH[(size_t)b * KCAT + EMB + ENC + iq] = hrH[b * DEC + iq];
        }
        int i0 = q * 512 + tid;
        gates[(size_t)b * GATES4 + i0]       = bcat[i0];
        gates[(size_t)b * GATES4 + i0 + 256] = bcat[i0 + 256];
    }

    const float Ab0 = Ab[0];
    const int f0 = q * 49;
    for (int f = f0 + warp; f < f0 + 49; f += 8) {
        const __half* u = uhsH + ((size_t)(b * NF + f)) * ATT;
        float a0 = 0.f, a1 = 0.f, a2 = 0.f, a3 = 0.f;
        #pragma unroll
        for (int kk = 0; kk < 4; ++kk) {
            int k = kk * 128 + lane * 4;
            uint2 uv = *reinterpret_cast<const uint2*>(u + k);
            float2 f01 = u2f2(uv.x);
            float2 f23 = u2f2(uv.y);
            float4 wv = *reinterpret_cast<const float4*>(&s_wah[k]);
            float4 av = *reinterpret_cast<const float4*>(&s_Aw[k]);
            a0 += htanh(f01.x + wv.x) * av.x;
            a1 += htanh(f01.y + wv.y) * av.y;
            a2 += htanh(f23.x + wv.z) * av.z;
            a3 += htanh(f23.y + wv.w) * av.w;
        }
        float acc = (a0 + a1) + (a2 + a3);
        #pragma unroll
        for (int o = 16; o; o >>= 1) acc += __shfl_xor_sync(0xffffffffu, acc, o);
        if (lane == 0) scores[b * NF + f] = acc + Ab0;
    }
}

// ---------------- ctx: softmax + context slice, grid (4, B), 512 threads ----
__global__ void __launch_bounds__(512)
ctx_kernel(const float* __restrict__ scores,
           const __half* __restrict__ featH,
           __half* __restrict__ incatH,
           float* __restrict__ alpha_out) {
    const int y = blockIdx.x;
    const int b = blockIdx.y;
    const int tid = threadIdx.x;
    const int warp = tid >> 5;
    const int lane = tid & 31;

    __shared__ float s_al[NF];
    __shared__ float s_red[16];
    __shared__ __align__(16) float4 s_part[4][128];

    float v = (tid < NF) ? scores[b * NF + tid] : -1e30f;
    float m = v;
    #pragma unroll
    for (int o = 16; o; o >>= 1) m = fmaxf(m, __shfl_xor_sync(0xffffffffu, m, o));
    if (lane == 0) s_red[warp] = m;
    __syncthreads();
    if (tid == 0) {
        float mm = s_red[0];
        #pragma unroll
        for (int w = 1; w < 16; ++w) mm = fmaxf(mm, s_red[w]);
        s_red[0] = mm;
    }
    __syncthreads();
    const float mx = s_red[0];
    __syncthreads();
    float e = (tid < NF) ? expf(v - mx) : 0.f;
    float s = e;
    #pragma unroll
    for (int o = 16; o; o >>= 1) s += __shfl_xor_sync(0xffffffffu, s, o);
    if (lane == 0) s_red[warp] = s;
    __syncthreads();
    if (tid == 0) {
        float ss = 0.f;
        #pragma unroll
        for (int w = 0; w < 16; ++w) ss += s_red[w];
        s_red[0] = ss;
    }
    __syncthreads();
    const float inv_denom = 1.0f / s_red[0];
    if (tid < NF) {
        float alpha = e * inv_denom;
        s_al[tid] = alpha;
        if (y == 0)
            alpha_out[(size_t)b * (TSTEPS * NF) + tid] = alpha;
    }
    __syncthreads();

    const int sub = tid >> 7;
    const int c4  = tid & 127;
    const int col = y * 512 + c4 * 4;
    const __half* fp = featH + (size_t)b * NF * ENC + col;
    float cx = 0.f, cy = 0.f, cz = 0.f, cw = 0.f;
    const int fs = sub * 49;
    #pragma unroll 7
    for (int f = fs; f < fs + 49; ++f) {
        uint2 fv = *reinterpret_cast<const uint2*>(fp + (size_t)f * ENC);
        float2 lo = u2f2(fv.x);
        float2 hi = u2f2(fv.y);
        float a = s_al[f];
        cx += a * lo.x; cy += a * lo.y; cz += a * hi.x; cw += a * hi.y;
    }
    s_part[sub][c4] = make_float4(cx, cy, cz, cw);
    __syncthreads();
    if (tid < 128) {
        float4 p0 = s_part[0][tid], p1 = s_part[1][tid];
        float4 p2 = s_part[2][tid], p3 = s_part[3][tid];
        uint2 o;
        o.x = h2u(__floats2half2_rn(p0.x + p1.x + p2.x + p3.x,
                                    p0.y + p1.y + p2.y + p3.y));
        o.y = h2u(__floats2half2_rn(p0.z + p1.z + p2.z + p3.z,
                                    p0.w + p1.w + p2.w + p3.w));
        *reinterpret_cast<uint2*>(
            &incatH[(size_t)b * KCAT + EMB + y * 512 + tid * 4]) = o;
    }
}

// ---------------- LSTM pointwise + wah bias-init ----------------
__global__ void lstm_kernel(const float* __restrict__ gates,
                            __half* __restrict__ hrH,
                            float* __restrict__ c,
                            float* __restrict__ wah,
                            const float* __restrict__ Wb) {
    int idx = blockIdx.x * blockDim.x + threadIdx.x;
    if (idx >= B * DEC) return;
    int b = idx / DEC;
    int n = idx - b * DEC;
    const float* g = gates + (size_t)b * GATES4;
    float i_ = g[n];
    float f_ = g[DEC + n];
    float gg = g[2 * DEC + n];
    float o_ = g[3 * DEC + n];
    float cc = c[idx];
    cc = sigmoidf_(f_) * cc + sigmoidf_(i_) * tanhf(gg);
    c[idx] = cc;
    hrH[idx] = __float2half_rn(sigmoidf_(o_) * tanhf(cc));
    wah[idx] = Wb[idx & (ATT - 1)];
}

// ---------------- launch ----------------
extern "C" void kernel_launch(void* const* d_in, const int* in_sizes, int n_in,
                              void* d_out, int out_size) {
    const float* features = (const float*)d_in[0];
    const int*   captions = (const int*)  d_in[1];
    const float* emb      = (const float*)d_in[2];
    const float* Uw       = (const float*)d_in[3];
    const float* Ub       = (const float*)d_in[4];
    const float* Ww       = (const float*)d_in[5];
    const float* Wb       = (const float*)d_in[6];
    const float* Aw       = (const float*)d_in[7];
    const float* Ab       = (const float*)d_in[8];
    const float* ih_w     = (const float*)d_in[9];
    const float* ih_b     = (const float*)d_in[10];
    const float* ic_w     = (const float*)d_in[11];
    const float* ic_b     = (const float*)d_in[12];
    const float* W_ih     = (const float*)d_in[13];
    const float* b_ih     = (const float*)d_in[14];
    const float* W_hh     = (const float*)d_in[15];
    const float* b_hh     = (const float*)d_in[16];
    const float* fcn_w    = (const float*)d_in[17];
    const float* fcn_b    = (const float*)d_in[18];
    float* out = (float*)d_out;

    float* S = nullptr;
    cudaGetSymbolAddress((void**)&S, g_scratch);
    __half*   uhsH   = reinterpret_cast<__half*>(S + OFF_UHSH);
    uint32_t* WcatP  = reinterpret_cast<uint32_t*>(S + OFF_WCATP);
    uint32_t* FcnP   = reinterpret_cast<uint32_t*>(S + OFF_FCNP);
    uint32_t* WwP    = reinterpret_cast<uint32_t*>(S + OFF_WWP);
    uint32_t* ihP    = reinterpret_cast<uint32_t*>(S + OFF_IHP);
    uint32_t* icP    = reinterpret_cast<uint32_t*>(S + OFF_ICP);
    uint32_t* UwP    = reinterpret_cast<uint32_t*>(S + OFF_UWP);
    __half*   featH  = reinterpret_cast<__half*>(S + OFF_FEATH);
    __half*   meanfH = reinterpret_cast<__half*>(S + OFF_MEANFH);
    float*    c      = S + OFF_CB;
    __half*   hrH[2] = { reinterpret_cast<__half*>(S + OFF_HRH0),
                         reinterpret_cast<__half*>(S + OFF_HRH1) };
    float*    wah    = S + OFF_WAH;
    __half*   incatH = reinterpret_cast<__half*>(S + OFF_INCATH);
    float*    gates  = S + OFF_GATES;
    float*    bcat   = S + OFF_BCAT;
    float*    sc     = S + OFF_SC;

    // ONE auxiliary stream (two tripped the teardown memory-baseline check).
    cudaStream_t s2;
    cudaStreamCreateWithFlags(&s2, cudaStreamNonBlocking);
    cudaEvent_t fork_ev[2], join_ev[2], start_ev, feat_ev, pjoin_ev;
    for (int i = 0; i < 2; ++i) {
        cudaEventCreateWithFlags(&fork_ev[i], cudaEventDisableTiming);
        cudaEventCreateWithFlags(&join_ev[i], cudaEventDisableTiming);
    }
    cudaEventCreateWithFlags(&start_ev, cudaEventDisableTiming);
    cudaEventCreateWithFlags(&feat_ev, cudaEventDisableTiming);
    cudaEventCreateWithFlags(&pjoin_ev, cudaEventDisableTiming);

    cudaEventRecord(start_ev, 0);
    cudaStreamWaitEvent(s2, start_ev, 0);

    // ---- prep, parallel across 2 streams; uhs GEMM is the 4th launch ----
    prep_wcat_kernel<<<2048, 256, 0, s2>>>(W_ih, W_hh, b_ih, b_hh, WcatP, bcat); // 1
    feat2h_kernel<<<(B * NF * ENC / 4 + 255) / 256, 256>>>(                      // 2
        features, featH, B * NF * ENC / 4);
    cudaEventRecord(feat_ev, 0);
    pack_weight_kernel<<<512, 256>>>(Uw, UwP, ENC, ATT);                         // 3
    h16_gemm<3><<<dim3(ATT / 128, (B * NF) / 64, 1), 256>>>(featH, ENC, UwP,     // 4 <- ncu
        ATT, nullptr, 0, Ub, uhsH, ATT, B * NF, ATT, ENC);
    // s2: remaining packs + h0/c0/wah0 chain
    pack_weight_kernel<<<512, 256, 0, s2>>>(ih_w, ihP, ENC, DEC);
    pack_weight_kernel<<<512, 256, 0, s2>>>(ic_w, icP, ENC, DEC);
    pack_weight_kernel<<<256, 256, 0, s2>>>(Ww, WwP, DEC, ATT);
    pack_weight_kernel<<<2048, 256, 0, s2>>>(fcn_w, FcnP, DEC, VOC);
    cudaStreamWaitEvent(s2, feat_ev, 0);
    meanf_h_kernel<<<(B * (ENC / 4) + 255) / 256, 256, 0, s2>>>(featH, meanfH);
    h16_gemm<3><<<dim3(DEC / 128, 1, 1), 256, 0, s2>>>(meanfH, ENC, ihP, DEC,
        nullptr, 0, ih_b, hrH[1], DEC, B, DEC, ENC);
    h16_gemm<1><<<dim3(DEC / 128, 1, 1), 256, 0, s2>>>(meanfH, ENC, icP, DEC,
        c, DEC, ic_b, nullptr, 0, B, DEC, ENC);
    h16_gemm<1><<<dim3(ATT / 128, 1, 1), 256, 0, s2>>>(hrH[1], DEC, WwP, ATT,
        wah, ATT, Wb, nullptr, 0, B, ATT, DEC);
    cudaEventRecord(pjoin_ev, s2);

    cudaStreamWaitEvent(0, pjoin_ev, 0);

    // ---- recurrent steps (R7/R10-proven structure) ----
    for (int t = 0; t < TSTEPS; ++t) {
        float* alpha_t = out + ALPHA_OFF + (size_t)t * NF;
        __half* hr_in  = hrH[(t + 1) & 1];
        __half* hr_out = hrH[t & 1];

        scores_kernel<<<dim3(4, B), 256>>>(uhsH, wah, Aw, Ab, captions, emb,
                                           bcat, hr_in, incatH, gates, sc, t);
        ctx_kernel<<<dim3(4, B), 512>>>(sc, featH, incatH, alpha_t);
        h16_gemm<0><<<dim3(GATES4 / 128, 1, 8), 256>>>(incatH, KCAT, WcatP, GATES4,
            gates, GATES4, nullptr, nullptr, 0, B, GATES4, KCAT);
        if (t >= 2) cudaStreamWaitEvent(0, join_ev[t & 1], 0);
        lstm_kernel<<<(B * DEC + 255) / 256, 256>>>(gates, hr_out, c, wah, Wb);
        cudaEventRecord(fork_ev[t & 1], 0);
        // wah = h_{t+1} @ Ww (+Wb already in wah), critical path, K-split 4
        h16_gemm<0><<<dim3(ATT / 128, 1, 4), 256>>>(hr_out, DEC, WwP, ATT,
            wah, ATT, nullptr, nullptr, 0, B, ATT, DEC);
        // preds_t — off critical path on s2
        cudaStreamWaitEvent(s2, fork_ev[t & 1], 0);
        h16_gemm<1><<<dim3((VOC + 127) / 128, 1, 1), 256, 0, s2>>>(hr_out, DEC,
            FcnP, VOC, out + (size_t)t * VOC, TSTEPS * VOC, fcn_b, nullptr, 0,
            B, VOC, DEC);
        cudaEventRecord(join_ev[t & 1], s2);
    }
    cudaStreamWaitEvent(0, join_ev[(TSTEPS - 1) & 1], 0);
    cudaStreamWaitEvent(0, join_ev[(TSTEPS - 2) & 1], 0);
}

// round 13
// speedup vs baseline: 1.6375x; 1.1881x over previous
#include <cuda_runtime.h>
#include <cuda_fp16.h>
#include <math.h>
#include <stdint.h>

// ---------------- problem constants ----------------
#define B    64
#define NF   196
#define ENC  2048
#define DEC  512
#define ATT  512
#define VOC  30000
#define EMB  512
#define TSTEPS 24
#define KCAT (EMB + ENC + DEC)   // 3072
#define GATES4 (4*DEC)           // 2048

#define ALPHA_OFF ((size_t)B * TSTEPS * VOC)

// ---------------- scratch layout (float-sized slots) ----------------
#define OFF_UHSH   ((size_t)0)
#define OFF_WCATP  (OFF_UHSH  + (size_t)B*NF*ATT/2)
#define OFF_FCNP   (OFF_WCATP + (size_t)(KCAT/2)*GATES4)
#define OFF_WWP    (OFF_FCNP  + (size_t)(DEC/2)*VOC)
#define OFF_IHP    (OFF_WWP   + (size_t)(DEC/2)*ATT)
#define OFF_ICP    (OFF_IHP   + (size_t)(ENC/2)*DEC)
#define OFF_UWP    (OFF_ICP   + (size_t)(ENC/2)*DEC)
#define OFF_FEATH  (OFF_UWP   + (size_t)(ENC/2)*ATT)
#define OFF_MEANFH (OFF_FEATH + (size_t)B*NF*ENC/2)
#define OFF_CB     (OFF_MEANFH+ (size_t)B*ENC/2)
#define OFF_HRALL  (OFF_CB    + (size_t)B*DEC)          // (TSTEPS+1)*B*DEC halves
#define OFF_WAH    (OFF_HRALL + (size_t)(TSTEPS+1)*B*DEC/2)
#define OFF_INCATH (OFF_WAH   + (size_t)B*ATT)
#define OFF_GATES  (OFF_INCATH+ (size_t)B*KCAT/2)
#define OFF_BCAT   (OFF_GATES + (size_t)B*GATES4)
#define OFF_SC     (OFF_BCAT  + (size_t)GATES4)
#define SCRATCH_TOTAL (OFF_SC + (size_t)B*NF)

__device__ __align__(16) float g_scratch[SCRATCH_TOTAL];

__device__ __forceinline__ float sigmoidf_(float x) {
    return 1.0f / (1.0f + expf(-x));
}
__device__ __forceinline__ float htanh(float x) {
    float y;
    asm("tanh.approx.f32 %0, %1;" : "=f"(y) : "f"(x));
    return y;
}
__device__ __forceinline__ uint32_t h2u(__half2 v) {
    return *reinterpret_cast<uint32_t*>(&v);
}
__device__ __forceinline__ float2 u2f2(uint32_t u) {
    return __half22float2(*reinterpret_cast<__half2*>(&u));
}

// ---------------- prep: pack W (K x N fp32) into k-pair half2 u32 ----------
__global__ void pack_weight_kernel(const float* __restrict__ W,
                                   uint32_t* __restrict__ P, int K, int N) {
    int total = (K / 2) * N;
    for (int i = blockIdx.x * blockDim.x + threadIdx.x; i < total;
         i += gridDim.x * blockDim.x) {
        int kp = i / N;
        int n = i - kp * N;
        P[i] = h2u(__floats2half2_rn(W[(size_t)(2 * kp) * N + n],
                                     W[(size_t)(2 * kp + 1) * N + n]));
    }
}

__global__ void prep_wcat_kernel(const float* __restrict__ W_ih,
                                 const float* __restrict__ W_hh,
                                 const float* __restrict__ b_ih,
                                 const float* __restrict__ b_hh,
                                 uint32_t* __restrict__ WcatP,
                                 float* __restrict__ bcat) {
    int total = (KCAT / 2) * GATES4;
    for (int i = blockIdx.x * blockDim.x + threadIdx.x; i < total;
         i += gridDim.x * blockDim.x) {
        int kp = i / GATES4;
        int n = i - kp * GATES4;
        int r0 = 2 * kp, r1 = 2 * kp + 1;
        float v0 = (r0 < EMB + ENC) ? W_ih[(size_t)r0 * GATES4 + n]
                                    : W_hh[(size_t)(r0 - EMB - ENC) * GATES4 + n];
        float v1 = (r1 < EMB + ENC) ? W_ih[(size_t)r1 * GATES4 + n]
                                    : W_hh[(size_t)(r1 - EMB - ENC) * GATES4 + n];
        WcatP[i] = h2u(__floats2half2_rn(v0, v1));
    }
    int idx = blockIdx.x * blockDim.x + threadIdx.x;
    if (idx < GATES4) bcat[idx] = b_ih[idx] + b_hh[idx];
}

__global__ void feat2h_kernel(const float* __restrict__ src,
                              __half* __restrict__ dst, int n4) {
    int i = blockIdx.x * blockDim.x + threadIdx.x;
    if (i < n4) {
        float4 v = reinterpret_cast<const float4*>(src)[i];
        uint2 o;
        o.x = h2u(__floats2half2_rn(v.x, v.y));
        o.y = h2u(__floats2half2_rn(v.z, v.w));
        reinterpret_cast<uint2*>(dst)[i] = o;
    }
}

__global__ void meanf_h_kernel(const __half* __restrict__ featH,
                               __half* __restrict__ meanfH) {
    int idx = blockIdx.x * blockDim.x + threadIdx.x;
    if (idx >= B * (ENC / 4)) return;
    int b = idx / (ENC / 4);
    int e4 = (idx - b * (ENC / 4)) * 4;
    const __half* p = featH + (size_t)b * NF * ENC + e4;
    float s0 = 0.f, s1 = 0.f, s2 = 0.f, s3 = 0.f;
    #pragma unroll 4
    for (int f = 0; f < NF; ++f) {
        uint2 v = *reinterpret_cast<const uint2*>(p + (size_t)f * ENC);
        float2 lo = u2f2(v.x);
        float2 hi = u2f2(v.y);
        s0 += lo.x; s1 += lo.y; s2 += hi.x; s3 += hi.y;
    }
    const float inv = 1.0f / (float)NF;
    uint2 o;
    o.x = h2u(__floats2half2_rn(s0 * inv, s1 * inv));
    o.y = h2u(__floats2half2_rn(s2 * inv, s3 * inv));
    *reinterpret_cast<uint2*>(meanfH + (size_t)b * ENC + e4) = o;
}

// ---------------- fp16 tensor-core GEMM (R10-proven double-buffered) ----------
// A row-major fp16 (lda halves); Bp k-pair packed u32 [K/2][ldb].
// MODE 0: atomicAdd fp32 C (K-split via gridDim.z)
// MODE 1: C = acc + bias (fp32)
// MODE 3: Ch = half(acc + bias)
// MODE 6: preds row-remap: row r (= t*64+b) -> C[(b*TSTEPS+t)*VOC + col] = acc+bias
template <int MODE>
__global__ void __launch_bounds__(256)
h16_gemm(const __half* __restrict__ A, int lda,
         const uint32_t* __restrict__ Bp, int ldb,
         float* __restrict__ C, int ldc,
         const float* __restrict__ bias,
         __half* __restrict__ Ch, int ldch,
         int M, int N, int K) {
    __shared__ __align__(16) uint32_t Af[1024];
    __shared__ __align__(16) uint32_t Bs[2][16][136];

    const int tid  = threadIdx.x;
    const int lane = tid & 31;
    const int warp = tid >> 5;
    const int wm = warp >> 2;
    const int wn = warp & 3;
    const int g = lane >> 2;
    const int t = lane & 3;

    const int m0 = blockIdx.y * 64;
    const int n0 = blockIdx.x * 128;
    const int chunks = (K / 32) / gridDim.z;
    const int kc0 = blockIdx.z * chunks;

    const int r = tid >> 2;
    const int cseg = tid & 3;
    const int amt = r >> 4;
    const int aks = cseg >> 1;
    const int ae = ((r >> 3) & 1) + ((cseg & 1) << 1);
    const int ag = r & 7;
    const int abase = ((((amt * 2 + aks) << 5) + (ag << 2)) << 2) + ae;

    float acc[2][4][4];
    #pragma unroll
    for (int mi = 0; mi < 2; ++mi)
        #pragma unroll
        for (int ni = 0; ni < 4; ++ni)
            #pragma unroll
            for (int q = 0; q < 4; ++q) acc[mi][ni][q] = 0.f;

    uint4 areg;
    {
        const int k0 = kc0 * 32;
        areg = *reinterpret_cast<const uint4*>(A + (size_t)(m0 + r) * lda + k0 + cseg * 8);
        const int kp0 = kc0 * 16;
        #pragma unroll
        for (int i = 0; i < 2; ++i) {
            int j = tid + i * 256;
            int br = j >> 5;
            int bc = (j & 31) * 4;
            int col = n0 + bc;
            const uint32_t* src = Bp + (size_t)(kp0 + br) * ldb + (col < N ? col : 0);
            uint32_t saddr = (uint32_t)__cvta_generic_to_shared(&Bs[0][br][bc]);
            int sz = (col < N) ? 16 : 0;
            asm volatile("cp.async.cg.shared.global [%0], [%1], 16, %2;\n"
                         :: "r"(saddr), "l"(src), "r"(sz));
        }
        asm volatile("cp.async.commit_group;\n");
        Af[abase + 0]  = areg.x;
        Af[abase + 4]  = areg.y;
        Af[abase + 8]  = areg.z;
        Af[abase + 12] = areg.w;
    }

    for (int cc = 0; cc < chunks; ++cc) {
        const int st = cc & 1;
        if (cc + 1 < chunks) {
            const int k0 = (kc0 + cc + 1) * 32;
            const int kp0 = (kc0 + cc + 1) * 16;
            #pragma unroll
            for (int i = 0; i < 2; ++i) {
                int j = tid + i * 256;
                int br = j >> 5;
                int bc = (j & 31) * 4;
                int col = n0 + bc;
                const uint32_t* src = Bp + (size_t)(kp0 + br) * ldb + (col < N ? col : 0);
                uint32_t saddr = (uint32_t)__cvta_generic_to_shared(&Bs[st ^ 1][br][bc]);
                int sz = (col < N) ? 16 : 0;
                asm volatile("cp.async.cg.shared.global [%0], [%1], 16, %2;\n"
                             :: "r"(saddr), "l"(src), "r"(sz));
            }
            areg = *reinterpret_cast<const uint4*>(A + (size_t)(m0 + r) * lda + k0 + cseg * 8);
        }
        asm volatile("cp.async.commit_group;\n");
        asm volatile("cp.async.wait_group 1;\n");
        __syncthreads();

        #pragma unroll
        for (int ks = 0; ks < 2; ++ks) {
            uint32_t af[2][4];
            #pragma unroll
            for (int mi = 0; mi < 2; ++mi) {
                int mt = wm * 2 + mi;
                uint4 a = *reinterpret_cast<const uint4*>(
                    &Af[(((mt * 2 + ks) << 5) + lane) << 2]);
                af[mi][0] = a.x; af[mi][1] = a.y; af[mi][2] = a.z; af[mi][3] = a.w;
            }
            #pragma unroll
            for (int ni = 0; ni < 4; ++ni) {
                int cB = wn * 32 + ni * 8 + g;
                uint32_t b0 = Bs[st][ks * 8 + t][cB];
                uint32_t b1 = Bs[st][ks * 8 + t + 4][cB];
                #pragma unroll
                for (int mi = 0; mi < 2; ++mi) {
                    asm volatile(
                        "mma.sync.aligned.m16n8k16.row.col.f32.f16.f16.f32 "
                        "{%0,%1,%2,%3}, {%4,%5,%6,%7}, {%8,%9}, {%0,%1,%2,%3};"
                        : "+f"(acc[mi][ni][0]), "+f"(acc[mi][ni][1]),
                          "+f"(acc[mi][ni][2]), "+f"(acc[mi][ni][3])
                        : "r"(af[mi][0]), "r"(af[mi][1]),
                          "r"(af[mi][2]), "r"(af[mi][3]),
                          "r"(b0), "r"(b1));
                }
            }
        }
        __syncthreads();
        if (cc + 1 < chunks) {
            Af[abase + 0]  = areg.x;
            Af[abase + 4]  = areg.y;
            Af[abase + 8]  = areg.z;
            Af[abase + 12] = areg.w;
        }
    }

    #pragma unroll
    for (int mi = 0; mi < 2; ++mi) {
        int r0 = m0 + wm * 32 + mi * 16 + g;
        #pragma unroll
        for (int ni = 0; ni < 4; ++ni) {
            int col = n0 + wn * 32 + ni * 8 + 2 * t;
            if (col >= N) continue;
            if (MODE == 0) {
                atomicAdd(&C[(size_t)r0 * ldc + col],           acc[mi][ni][0]);
                atomicAdd(&C[(size_t)r0 * ldc + col + 1],       acc[mi][ni][1]);
                atomicAdd(&C[(size_t)(r0 + 8) * ldc + col],     acc[mi][ni][2]);
                atomicAdd(&C[(size_t)(r0 + 8) * ldc + col + 1], acc[mi][ni][3]);
            } else if (MODE == 1) {
                float bv0 = bias[col], bv1 = bias[col + 1];
                *reinterpret_cast<float2*>(&C[(size_t)r0 * ldc + col]) =
                    make_float2(acc[mi][ni][0] + bv0, acc[mi][ni][1] + bv1);
                *reinterpret_cast<float2*>(&C[(size_t)(r0 + 8) * ldc + col]) =
                    make_float2(acc[mi][ni][2] + bv0, acc[mi][ni][3] + bv1);
            } else if (MODE == 3) {
                float bv0 = bias[col], bv1 = bias[col + 1];
                *reinterpret_cast<__half2*>(&Ch[(size_t)r0 * ldch + col]) =
                    __floats2half2_rn(acc[mi][ni][0] + bv0, acc[mi][ni][1] + bv1);
                *reinterpret_cast<__half2*>(&Ch[(size_t)(r0 + 8) * ldch + col]) =
                    __floats2half2_rn(acc[mi][ni][2] + bv0, acc[mi][ni][3] + bv1);
            } else {  // MODE 6: row r = t*B + b -> out[(b*TSTEPS + t)*VOC + col]
                float bv0 = bias[col], bv1 = bias[col + 1];
                size_t o0 = (size_t)(r0 & 63) * ((size_t)TSTEPS * VOC)
                          + (size_t)(r0 >> 6) * VOC + col;
                size_t o1 = (size_t)((r0 + 8) & 63) * ((size_t)TSTEPS * VOC)
                          + (size_t)((r0 + 8) >> 6) * VOC + col;
                *reinterpret_cast<float2*>(&C[o0]) =
                    make_float2(acc[mi][ni][0] + bv0, acc[mi][ni][1] + bv1);
                *reinterpret_cast<float2*>(&C[o1]) =
                    make_float2(acc[mi][ni][2] + bv0, acc[mi][ni][3] + bv1);
            }
        }
    }
}

// ---------------- scores: grid (4, B), 256 threads ----------------
__global__ void __launch_bounds__(256)
scores_kernel(const __half* __restrict__ uhsH,
              const float* __restrict__ wah,     // includes Wb bias
              const float* __restrict__ Aw,
              const float* __restrict__ Ab,
              const int* __restrict__ captions,
              const float* __restrict__ emb,
              const float* __restrict__ bcat,
              const __half* __restrict__ hrH,
              __half* __restrict__ incatH,
              float* __restrict__ gates,
              float* __restrict__ scores,
              int t) {
    const int q = blockIdx.x;
    const int b = blockIdx.y;
    const int tid = threadIdx.x;
    const int warp = tid >> 5;
    const int lane = tid & 31;

    __shared__ __align__(16) float s_wah[ATT];
    __shared__ __align__(16) float s_Aw[ATT];

    for (int i = tid; i < ATT; i += 256) {
        s_wah[i] = wah[b * ATT + i];
        s_Aw[i]  = Aw[i];
    }
    __syncthreads();

    {
        int tok = captions[b * (TSTEPS + 1) + t];
        if (tid < 128) {
            int iq = q * 128 + tid;
            incatH[(size_t)b * KCAT + iq] = __float2half_rn(emb[(size_t)tok * EMB + iq]);
            incatH[(size_t)b * KCAT + EMB + ENC + iq] = hrH[b * DEC + iq];
        }
        int i0 = q * 512 + tid;
        gates[(size_t)b * GATES4 + i0]       = bcat[i0];
        gates[(size_t)b * GATES4 + i0 + 256] = bcat[i0 + 256];
    }

    const float Ab0 = Ab[0];
    const int f0 = q * 49;
    for (int f = f0 + warp; f < f0 + 49; f += 8) {
        const __half* u = uhsH + ((size_t)(b * NF + f)) * ATT;
        float a0 = 0.f, a1 = 0.f, a2 = 0.f, a3 = 0.f;
        #pragma unroll
        for (int kk = 0; kk < 4; ++kk) {
            int k = kk * 128 + lane * 4;
            uint2 uv = *reinterpret_cast<const uint2*>(u + k);
            float2 f01 = u2f2(uv.x);
            float2 f23 = u2f2(uv.y);
            float4 wv = *reinterpret_cast<const float4*>(&s_wah[k]);
            float4 av = *reinterpret_cast<const float4*>(&s_Aw[k]);
            a0 += htanh(f01.x + wv.x) * av.x;
            a1 += htanh(f01.y + wv.y) * av.y;
            a2 += htanh(f23.x + wv.z) * av.z;
            a3 += htanh(f23.y + wv.w) * av.w;
        }
        float acc = (a0 + a1) + (a2 + a3);
        #pragma unroll
        for (int o = 16; o; o >>= 1) acc += __shfl_xor_sync(0xffffffffu, acc, o);
        if (lane == 0) scores[b * NF + f] = acc + Ab0;
    }
}

// ---------------- ctx: softmax + context slice, grid (4, B), 512 threads ----
__global__ void __launch_bounds__(512)
ctx_kernel(const float* __restrict__ scores,
           const __half* __restrict__ featH,
           __half* __restrict__ incatH,
           float* __restrict__ alpha_out) {
    const int y = blockIdx.x;
    const int b = blockIdx.y;
    const int tid = threadIdx.x;
    const int warp = tid >> 5;
    const int lane = tid & 31;

    __shared__ float s_al[NF];
    __shared__ float s_red[16];
    __shared__ __align__(16) float4 s_part[4][128];

    float v = (tid < NF) ? scores[b * NF + tid] : -1e30f;
    float m = v;
    #pragma unroll
    for (int o = 16; o; o >>= 1) m = fmaxf(m, __shfl_xor_sync(0xffffffffu, m, o));
    if (lane == 0) s_red[warp] = m;
    __syncthreads();
    if (tid == 0) {
        float mm = s_red[0];
        #pragma unroll
        for (int w = 1; w < 16; ++w) mm = fmaxf(mm, s_red[w]);
        s_red[0] = mm;
    }
    __syncthreads();
    const float mx = s_red[0];
    __syncthreads();
    float e = (tid < NF) ? expf(v - mx) : 0.f;
    float s = e;
    #pragma unroll
    for (int o = 16; o; o >>= 1) s += __shfl_xor_sync(0xffffffffu, s, o);
    if (lane == 0) s_red[warp] = s;
    __syncthreads();
    if (tid == 0) {
        float ss = 0.f;
        #pragma unroll
        for (int w = 0; w < 16; ++w) ss += s_red[w];
        s_red[0] = ss;
    }
    __syncthreads();
    const float inv_denom = 1.0f / s_red[0];
    if (tid < NF) {
        float alpha = e * inv_denom;
        s_al[tid] = alpha;
        if (y == 0)
            alpha_out[(size_t)b * (TSTEPS * NF) + tid] = alpha;
    }
    __syncthreads();

    const int sub = tid >> 7;
    const int c4  = tid & 127;
    const int col = y * 512 + c4 * 4;
    const __half* fp = featH + (size_t)b * NF * ENC + col;
    float cx = 0.f, cy = 0.f, cz = 0.f, cw = 0.f;
    const int fs = sub * 49;
    #pragma unroll 7
    for (int f = fs; f < fs + 49; ++f) {
        uint2 fv = *reinterpret_cast<const uint2*>(fp + (size_t)f * ENC);
        float2 lo = u2f2(fv.x);
        float2 hi = u2f2(fv.y);
        float a = s_al[f];
        cx += a * lo.x; cy += a * lo.y; cz += a * hi.x; cw += a * hi.y;
    }
    s_part[sub][c4] = make_float4(cx, cy, cz, cw);
    __syncthreads();
    if (tid < 128) {
        float4 p0 = s_part[0][tid], p1 = s_part[1][tid];
        float4 p2 = s_part[2][tid], p3 = s_part[3][tid];
        uint2 o;
        o.x = h2u(__floats2half2_rn(p0.x + p1.x + p2.x + p3.x,
                                    p0.y + p1.y + p2.y + p3.y));
        o.y = h2u(__floats2half2_rn(p0.z + p1.z + p2.z + p3.z,
                                    p0.w + p1.w + p2.w + p3.w));
        *reinterpret_cast<uint2*>(
            &incatH[(size_t)b * KCAT + EMB + y * 512 + tid * 4]) = o;
    }
}

// ---------------- LSTM pointwise + wah bias-init ----------------
__global__ void lstm_kernel(const float* __restrict__ gates,
                            __half* __restrict__ hrH,
                            float* __restrict__ c,
                            float* __restrict__ wah,
                            const float* __restrict__ Wb) {
    int idx = blockIdx.x * blockDim.x + threadIdx.x;
    if (idx >= B * DEC) return;
    int b = idx / DEC;
    int n = idx - b * DEC;
    const float* g = gates + (size_t)b * GATES4;
    float i_ = g[n];
    float f_ = g[DEC + n];
    float gg = g[2 * DEC + n];
    float o_ = g[3 * DEC + n];
    float cc = c[idx];
    cc = sigmoidf_(f_) * cc + sigmoidf_(i_) * tanhf(gg);
    c[idx] = cc;
    hrH[idx] = __float2half_rn(sigmoidf_(o_) * tanhf(cc));
    wah[idx] = Wb[idx & (ATT - 1)];
}

// ---------------- launch ----------------
extern "C" void kernel_launch(void* const* d_in, const int* in_sizes, int n_in,
                              void* d_out, int out_size) {
    const float* features = (const float*)d_in[0];
    const int*   captions = (const int*)  d_in[1];
    const float* emb      = (const float*)d_in[2];
    const float* Uw       = (const float*)d_in[3];
    const float* Ub       = (const float*)d_in[4];
    const float* Ww       = (const float*)d_in[5];
    const float* Wb       = (const float*)d_in[6];
    const float* Aw       = (const float*)d_in[7];
    const float* Ab       = (const float*)d_in[8];
    const float* ih_w     = (const float*)d_in[9];
    const float* ih_b     = (const float*)d_in[10];
    const float* ic_w     = (const float*)d_in[11];
    const float* ic_b     = (const float*)d_in[12];
    const float* W_ih     = (const float*)d_in[13];
    const float* b_ih     = (const float*)d_in[14];
    const float* W_hh     = (const float*)d_in[15];
    const float* b_hh     = (const float*)d_in[16];
    const float* fcn_w    = (const float*)d_in[17];
    const float* fcn_b    = (const float*)d_in[18];
    float* out = (float*)d_out;

    float* S = nullptr;
    cudaGetSymbolAddress((void**)&S, g_scratch);
    __half*   uhsH   = reinterpret_cast<__half*>(S + OFF_UHSH);
    uint32_t* WcatP  = reinterpret_cast<uint32_t*>(S + OFF_WCATP);
    uint32_t* FcnP   = reinterpret_cast<uint32_t*>(S + OFF_FCNP);
    uint32_t* WwP    = reinterpret_cast<uint32_t*>(S + OFF_WWP);
    uint32_t* ihP    = reinterpret_cast<uint32_t*>(S + OFF_IHP);
    uint32_t* icP    = reinterpret_cast<uint32_t*>(S + OFF_ICP);
    uint32_t* UwP    = reinterpret_cast<uint32_t*>(S + OFF_UWP);
    __half*   featH  = reinterpret_cast<__half*>(S + OFF_FEATH);
    __half*   meanfH = reinterpret_cast<__half*>(S + OFF_MEANFH);
    float*    c      = S + OFF_CB;
    __half*   hrAll  = reinterpret_cast<__half*>(S + OFF_HRALL);
    float*    wah    = S + OFF_WAH;
    __half*   incatH = reinterpret_cast<__half*>(S + OFF_INCATH);
    float*    gates  = S + OFF_GATES;
    float*    bcat   = S + OFF_BCAT;
    float*    sc     = S + OFF_SC;

    // ONE auxiliary stream (prep overlap only; loop is single-stream now).
    cudaStream_t s2;
    cudaStreamCreateWithFlags(&s2, cudaStreamNonBlocking);
    cudaEvent_t start_ev, feat_ev, pjoin_ev;
    cudaEventCreateWithFlags(&start_ev, cudaEventDisableTiming);
    cudaEventCreateWithFlags(&feat_ev, cudaEventDisableTiming);
    cudaEventCreateWithFlags(&pjoin_ev, cudaEventDisableTiming);

    cudaEventRecord(start_ev, 0);
    cudaStreamWaitEvent(s2, start_ev, 0);

    // ---- prep, parallel across 2 streams; uhs GEMM is the 4th launch ----
    prep_wcat_kernel<<<2048, 256, 0, s2>>>(W_ih, W_hh, b_ih, b_hh, WcatP, bcat); // 1
    feat2h_kernel<<<(B * NF * ENC / 4 + 255) / 256, 256>>>(                      // 2
        features, featH, B * NF * ENC / 4);
    cudaEventRecord(feat_ev, 0);
    pack_weight_kernel<<<512, 256>>>(Uw, UwP, ENC, ATT);                         // 3
    h16_gemm<3><<<dim3(ATT / 128, (B * NF) / 64, 1), 256>>>(featH, ENC, UwP,     // 4 <- ncu
        ATT, nullptr, 0, Ub, uhsH, ATT, B * NF, ATT, ENC);
    // s2: remaining packs + h0/c0/wah0 chain
    pack_weight_kernel<<<512, 256, 0, s2>>>(ih_w, ihP, ENC, DEC);
    pack_weight_kernel<<<512, 256, 0, s2>>>(ic_w, icP, ENC, DEC);
    pack_weight_kernel<<<256, 256, 0, s2>>>(Ww, WwP, DEC, ATT);
    pack_weight_kernel<<<2048, 256, 0, s2>>>(fcn_w, FcnP, DEC, VOC);
    cudaStreamWaitEvent(s2, feat_ev, 0);
    meanf_h_kernel<<<(B * (ENC / 4) + 255) / 256, 256, 0, s2>>>(featH, meanfH);
    h16_gemm<3><<<dim3(DEC / 128, 1, 1), 256, 0, s2>>>(meanfH, ENC, ihP, DEC,
        nullptr, 0, ih_b, hrAll, DEC, B, DEC, ENC);                 // h0 -> hrAll[0]
    h16_gemm<1><<<dim3(DEC / 128, 1, 1), 256, 0, s2>>>(meanfH, ENC, icP, DEC,
        c, DEC, ic_b, nullptr, 0, B, DEC, ENC);
    h16_gemm<1><<<dim3(ATT / 128, 1, 1), 256, 0, s2>>>(hrAll, DEC, WwP, ATT,
        wah, ATT, Wb, nullptr, 0, B, ATT, DEC);                     // wah0 (+Wb)
    cudaEventRecord(pjoin_ev, s2);

    cudaStreamWaitEvent(0, pjoin_ev, 0);

    // ---- recurrent steps (single stream; preds deferred) ----
    for (int t = 0; t < TSTEPS; ++t) {
        float* alpha_t = out + ALPHA_OFF + (size_t)t * NF;
        __half* hr_in  = hrAll + (size_t)t * B * DEC;
        __half* hr_out = hrAll + (size_t)(t + 1) * B * DEC;

        scores_kernel<<<dim3(4, B), 256>>>(uhsH, wah, Aw, Ab, captions, emb,
                                           bcat, hr_in, incatH, gates, sc, t);
        ctx_kernel<<<dim3(4, B), 512>>>(sc, featH, incatH, alpha_t);
        h16_gemm<0><<<dim3(GATES4 / 128, 1, 8), 256>>>(incatH, KCAT, WcatP, GATES4,
            gates, GATES4, nullptr, nullptr, 0, B, GATES4, KCAT);
        lstm_kernel<<<(B * DEC + 255) / 256, 256>>>(gates, hr_out, c, wah, Wb);
        // wah = h_{t+1} @ Ww (+Wb already in wah), K-split 4 (skip on last step)
        if (t + 1 < TSTEPS)
            h16_gemm<0><<<dim3(ATT / 128, 1, 4), 256>>>(hr_out, DEC, WwP, ATT,
                wah, ATT, nullptr, nullptr, 0, B, ATT, DEC);
    }

    // ---- batched preds: [all h_1..h_24] @ fcn_w + fcn_b, M = 1536 ----
    // row r = t*64 + b  ->  out[(b*TSTEPS + t)*VOC + col]  (MODE 6)
    h16_gemm<6><<<dim3((VOC + 127) / 128, (B * TSTEPS) / 64, 1), 256>>>(
        hrAll + (size_t)B * DEC, DEC, FcnP, VOC,
        out, 0, fcn_b, nullptr, 0, B * TSTEPS, VOC, DEC);
}

// round 14
// speedup vs baseline: 1.6563x; 1.0115x over previous
#include <cuda_runtime.h>
#include <cuda_fp16.h>
#include <math.h>
#include <stdint.h>

// ---------------- problem constants ----------------
#define B    64
#define NF   196
#define ENC  2048
#define DEC  512
#define ATT  512
#define VOC  30000
#define EMB  512
#define TSTEPS 24
#define KCAT (EMB + ENC + DEC)   // 3072
#define GATES4 (4*DEC)           // 2048

#define ALPHA_OFF ((size_t)B * TSTEPS * VOC)

// ---------------- scratch layout (float-sized slots) ----------------
#define OFF_UHSH   ((size_t)0)
#define OFF_WCATP  (OFF_UHSH  + (size_t)B*NF*ATT/2)
#define OFF_FCNP   (OFF_WCATP + (size_t)(KCAT/2)*GATES4)
#define OFF_WWP    (OFF_FCNP  + (size_t)(DEC/2)*VOC)
#define OFF_IHP    (OFF_WWP   + (size_t)(DEC/2)*ATT)
#define OFF_ICP    (OFF_IHP   + (size_t)(ENC/2)*DEC)
#define OFF_UWP    (OFF_ICP   + (size_t)(ENC/2)*DEC)
#define OFF_FEATH  (OFF_UWP   + (size_t)(ENC/2)*ATT)
#define OFF_MEANFH (OFF_FEATH + (size_t)B*NF*ENC/2)
#define OFF_CB     (OFF_MEANFH+ (size_t)B*ENC/2)
#define OFF_HRALL  (OFF_CB    + (size_t)B*DEC)          // (TSTEPS+1)*B*DEC halves
#define OFF_WAH    (OFF_HRALL + (size_t)(TSTEPS+1)*B*DEC/2)
#define OFF_INCATH (OFF_WAH   + (size_t)B*ATT)
#define OFF_GATES  (OFF_INCATH+ (size_t)B*KCAT/2)
#define OFF_BCAT   (OFF_GATES + (size_t)B*GATES4)
#define OFF_SC     (OFF_BCAT  + (size_t)GATES4)
#define SCRATCH_TOTAL (OFF_SC + (size_t)B*NF)

__device__ __align__(16) float g_scratch[SCRATCH_TOTAL];

__device__ __forceinline__ float sigmoidf_(float x) {
    return 1.0f / (1.0f + expf(-x));
}
__device__ __forceinline__ uint32_t h2u(__half2 v) {
    return *reinterpret_cast<uint32_t*>(&v);
}
__device__ __forceinline__ float2 u2f2(uint32_t u) {
    return __half22float2(*reinterpret_cast<__half2*>(&u));
}
__device__ __forceinline__ uint32_t htanh2(uint32_t x) {
    uint32_t y;
    asm("tanh.approx.f16x2 %0, %1;" : "=r"(y) : "r"(x));
    return y;
}
__device__ __forceinline__ uint32_t hadd2u(uint32_t a, uint32_t b) {
    __half2 r = __hadd2(*reinterpret_cast<__half2*>(&a),
                        *reinterpret_cast<__half2*>(&b));
    return h2u(r);
}

// ---------------- prep kernels ----------------
__global__ void pack_weight_kernel(const float* __restrict__ W,
                                   uint32_t* __restrict__ P, int K, int N) {
    int total = (K / 2) * N;
    for (int i = blockIdx.x * blockDim.x + threadIdx.x; i < total;
         i += gridDim.x * blockDim.x) {
        int kp = i / N;
        int n = i - kp * N;
        P[i] = h2u(__floats2half2_rn(W[(size_t)(2 * kp) * N + n],
                                     W[(size_t)(2 * kp + 1) * N + n]));
    }
}

__global__ void prep_wcat_kernel(const float* __restrict__ W_ih,
                                 const float* __restrict__ W_hh,
                                 const float* __restrict__ b_ih,
                                 const float* __restrict__ b_hh,
                                 uint32_t* __restrict__ WcatP,
                                 float* __restrict__ bcat) {
    int total = (KCAT / 2) * GATES4;
    for (int i = blockIdx.x * blockDim.x + threadIdx.x; i < total;
         i += gridDim.x * blockDim.x) {
        int kp = i / GATES4;
        int n = i - kp * GATES4;
        int r0 = 2 * kp, r1 = 2 * kp + 1;
        float v0 = (r0 < EMB + ENC) ? W_ih[(size_t)r0 * GATES4 + n]
                                    : W_hh[(size_t)(r0 - EMB - ENC) * GATES4 + n];
        float v1 = (r1 < EMB + ENC) ? W_ih[(size_t)r1 * GATES4 + n]
                                    : W_hh[(size_t)(r1 - EMB - ENC) * GATES4 + n];
        WcatP[i] = h2u(__floats2half2_rn(v0, v1));
    }
    int idx = blockIdx.x * blockDim.x + threadIdx.x;
    if (idx < GATES4) bcat[idx] = b_ih[idx] + b_hh[idx];
}

__global__ void feat2h_kernel(const float* __restrict__ src,
                              __half* __restrict__ dst, int n4) {
    int i = blockIdx.x * blockDim.x + threadIdx.x;
    if (i < n4) {
        float4 v = reinterpret_cast<const float4*>(src)[i];
        uint2 o;
        o.x = h2u(__floats2half2_rn(v.x, v.y));
        o.y = h2u(__floats2half2_rn(v.z, v.w));
        reinterpret_cast<uint2*>(dst)[i] = o;
    }
}

__global__ void meanf_h_kernel(const __half* __restrict__ featH,
                               __half* __restrict__ meanfH) {
    int idx = blockIdx.x * blockDim.x + threadIdx.x;
    if (idx >= B * (ENC / 4)) return;
    int b = idx / (ENC / 4);
    int e4 = (idx - b * (ENC / 4)) * 4;
    const __half* p = featH + (size_t)b * NF * ENC + e4;
    float s0 = 0.f, s1 = 0.f, s2 = 0.f, s3 = 0.f;
    #pragma unroll 4
    for (int f = 0; f < NF; ++f) {
        uint2 v = *reinterpret_cast<const uint2*>(p + (size_t)f * ENC);
        float2 lo = u2f2(v.x);
        float2 hi = u2f2(v.y);
        s0 += lo.x; s1 += lo.y; s2 += hi.x; s3 += hi.y;
    }
    const float inv = 1.0f / (float)NF;
    uint2 o;
    o.x = h2u(__floats2half2_rn(s0 * inv, s1 * inv));
    o.y = h2u(__floats2half2_rn(s2 * inv, s3 * inv));
    *reinterpret_cast<uint2*>(meanfH + (size_t)b * ENC + e4) = o;
}

// ---------------- 64x128 fp16 GEMM (proven; small M uses) ----------------
// MODE 0: atomicAdd fp32 C (K-split via gridDim.z)
// MODE 1: C = acc + bias (fp32)
// MODE 3: Ch = half(acc + bias)
template <int MODE>
__global__ void __launch_bounds__(256)
h16_gemm(const __half* __restrict__ A, int lda,
         const uint32_t* __restrict__ Bp, int ldb,
         float* __restrict__ C, int ldc,
         const float* __restrict__ bias,
         __half* __restrict__ Ch, int ldch,
         int M, int N, int K) {
    __shared__ __align__(16) uint32_t Af[1024];
    __shared__ __align__(16) uint32_t Bs[2][16][136];

    const int tid  = threadIdx.x;
    const int lane = tid & 31;
    const int warp = tid >> 5;
    const int wm = warp >> 2;
    const int wn = warp & 3;
    const int g = lane >> 2;
    const int t = lane & 3;

    const int m0 = blockIdx.y * 64;
    const int n0 = blockIdx.x * 128;
    const int chunks = (K / 32) / gridDim.z;
    const int kc0 = blockIdx.z * chunks;

    const int r = tid >> 2;
    const int cseg = tid & 3;
    const int amt = r >> 4;
    const int aks = cseg >> 1;
    const int ae = ((r >> 3) & 1) + ((cseg & 1) << 1);
    const int ag = r & 7;
    const int abase = ((((amt * 2 + aks) << 5) + (ag << 2)) << 2) + ae;

    float acc[2][4][4];
    #pragma unroll
    for (int mi = 0; mi < 2; ++mi)
        #pragma unroll
        for (int ni = 0; ni < 4; ++ni)
            #pragma unroll
            for (int q = 0; q < 4; ++q) acc[mi][ni][q] = 0.f;

    uint4 areg;
    {
        const int k0 = kc0 * 32;
        areg = *reinterpret_cast<const uint4*>(A + (size_t)(m0 + r) * lda + k0 + cseg * 8);
        const int kp0 = kc0 * 16;
        #pragma unroll
        for (int i = 0; i < 2; ++i) {
            int j = tid + i * 256;
            int br = j >> 5;
            int bc = (j & 31) * 4;
            int col = n0 + bc;
            const uint32_t* src = Bp + (size_t)(kp0 + br) * ldb + (col < N ? col : 0);
            uint32_t saddr = (uint32_t)__cvta_generic_to_shared(&Bs[0][br][bc]);
            int sz = (col < N) ? 16 : 0;
            asm volatile("cp.async.cg.shared.global [%0], [%1], 16, %2;\n"
                         :: "r"(saddr), "l"(src), "r"(sz));
        }
        asm volatile("cp.async.commit_group;\n");
        Af[abase + 0]  = areg.x;
        Af[abase + 4]  = areg.y;
        Af[abase + 8]  = areg.z;
        Af[abase + 12] = areg.w;
    }

    for (int cc = 0; cc < chunks; ++cc) {
        const int st = cc & 1;
        if (cc + 1 < chunks) {
            const int k0 = (kc0 + cc + 1) * 32;
            const int kp0 = (kc0 + cc + 1) * 16;
            #pragma unroll
            for (int i = 0; i < 2; ++i) {
                int j = tid + i * 256;
                int br = j >> 5;
                int bc = (j & 31) * 4;
                int col = n0 + bc;
                const uint32_t* src = Bp + (size_t)(kp0 + br) * ldb + (col < N ? col : 0);
                uint32_t saddr = (uint32_t)__cvta_generic_to_shared(&Bs[st ^ 1][br][bc]);
                int sz = (col < N) ? 16 : 0;
                asm volatile("cp.async.cg.shared.global [%0], [%1], 16, %2;\n"
                             :: "r"(saddr), "l"(src), "r"(sz));
            }
            areg = *reinterpret_cast<const uint4*>(A + (size_t)(m0 + r) * lda + k0 + cseg * 8);
        }
        asm volatile("cp.async.commit_group;\n");
        asm volatile("cp.async.wait_group 1;\n");
        __syncthreads();

        #pragma unroll
        for (int ks = 0; ks < 2; ++ks) {
            uint32_t af[2][4];
            #pragma unroll
            for (int mi = 0; mi < 2; ++mi) {
                int mt = wm * 2 + mi;
                uint4 a = *reinterpret_cast<const uint4*>(
                    &Af[(((mt * 2 + ks) << 5) + lane) << 2]);
                af[mi][0] = a.x; af[mi][1] = a.y; af[mi][2] = a.z; af[mi][3] = a.w;
            }
            #pragma unroll
            for (int ni = 0; ni < 4; ++ni) {
                int cB = wn * 32 + ni * 8 + g;
                uint32_t b0 = Bs[st][ks * 8 + t][cB];
                uint32_t b1 = Bs[st][ks * 8 + t + 4][cB];
                #pragma unroll
                for (int mi = 0; mi < 2; ++mi) {
                    asm volatile(
                        "mma.sync.aligned.m16n8k16.row.col.f32.f16.f16.f32 "
                        "{%0,%1,%2,%3}, {%4,%5,%6,%7}, {%8,%9}, {%0,%1,%2,%3};"
                        : "+f"(acc[mi][ni][0]), "+f"(acc[mi][ni][1]),
                          "+f"(acc[mi][ni][2]), "+f"(acc[mi][ni][3])
                        : "r"(af[mi][0]), "r"(af[mi][1]),
                          "r"(af[mi][2]), "r"(af[mi][3]),
                          "r"(b0), "r"(b1));
                }
            }
        }
        __syncthreads();
        if (cc + 1 < chunks) {
            Af[abase + 0]  = areg.x;
            Af[abase + 4]  = areg.y;
            Af[abase + 8]  = areg.z;
            Af[abase + 12] = areg.w;
        }
    }

    #pragma unroll
    for (int mi = 0; mi < 2; ++mi) {
        int r0 = m0 + wm * 32 + mi * 16 + g;
        #pragma unroll
        for (int ni = 0; ni < 4; ++ni) {
            int col = n0 + wn * 32 + ni * 8 + 2 * t;
            if (col >= N) continue;
            if (MODE == 0) {
                atomicAdd(&C[(size_t)r0 * ldc + col],           acc[mi][ni][0]);
                atomicAdd(&C[(size_t)r0 * ldc + col + 1],       acc[mi][ni][1]);
                atomicAdd(&C[(size_t)(r0 + 8) * ldc + col],     acc[mi][ni][2]);
                atomicAdd(&C[(size_t)(r0 + 8) * ldc + col + 1], acc[mi][ni][3]);
            } else if (MODE == 1) {
                float bv0 = bias[col], bv1 = bias[col + 1];
                *reinterpret_cast<float2*>(&C[(size_t)r0 * ldc + col]) =
                    make_float2(acc[mi][ni][0] + bv0, acc[mi][ni][1] + bv1);
                *reinterpret_cast<float2*>(&C[(size_t)(r0 + 8) * ldc + col]) =
                    make_float2(acc[mi][ni][2] + bv0, acc[mi][ni][3] + bv1);
            } else {
                float bv0 = bias[col], bv1 = bias[col + 1];
                *reinterpret_cast<__half2*>(&Ch[(size_t)r0 * ldch + col]) =
                    __floats2half2_rn(acc[mi][ni][0] + bv0, acc[mi][ni][1] + bv1);
                *reinterpret_cast<__half2*>(&Ch[(size_t)(r0 + 8) * ldch + col]) =
                    __floats2half2_rn(acc[mi][ni][2] + bv0, acc[mi][ni][3] + bv1);
            }
        }
    }
}

// ---------------- 128x128 fp16 GEMM (big tiles; uhs + batched preds) --------
// 8 warps as (wm 0..3) x (wn 0..1); warp tile 32x64. Requires M%128==0.
// MODE 3: Ch = half(acc + bias)
// MODE 6: preds row-remap: row r (= t*64+b) -> C[(b*TSTEPS+t)*VOC + col]
template <int MODE>
__global__ void __launch_bounds__(256)
h16_gemm128(const __half* __restrict__ A, int lda,
            const uint32_t* __restrict__ Bp, int ldb,
            float* __restrict__ C,
            const float* __restrict__ bias,
            __half* __restrict__ Ch, int ldch,
            int M, int N, int K) {
    __shared__ __align__(16) uint32_t Af[2048];          // 8 KB, 128 rows frag
    __shared__ __align__(16) uint32_t Bs[2][16][136];

    const int tid  = threadIdx.x;
    const int lane = tid & 31;
    const int warp = tid >> 5;
    const int wm = warp >> 1;          // 0..3
    const int wn = warp & 1;           // 0..1
    const int g = lane >> 2;
    const int t = lane & 3;

    const int m0 = blockIdx.y * 128;
    const int n0 = blockIdx.x * 128;
    const int chunks = K / 32;

    const int r = tid >> 2;            // 0..63
    const int cseg = tid & 3;
    const int aks = cseg >> 1;
    const int eA = (cseg & 1) << 1;
    // two rows: r and r+64
    const int r2 = r + 64;
    const int ab1 = ((((r >> 4) * 2 + aks) << 5) + ((r & 7) << 2)) * 4
                  + ((r >> 3) & 1) + eA;
    const int ab2 = ((((r2 >> 4) * 2 + aks) << 5) + ((r2 & 7) << 2)) * 4
                  + ((r2 >> 3) & 1) + eA;

    float acc[2][8][4];
    #pragma unroll
    for (int mi = 0; mi < 2; ++mi)
        #pragma unroll
        for (int ni = 0; ni < 8; ++ni)
            #pragma unroll
            for (int q = 0; q < 4; ++q) acc[mi][ni][q] = 0.f;

    uint4 areg0, areg1;
    {
        const int k0 = 0;
        areg0 = *reinterpret_cast<const uint4*>(A + (size_t)(m0 + r)  * lda + k0 + cseg * 8);
        areg1 = *reinterpret_cast<const uint4*>(A + (size_t)(m0 + r2) * lda + k0 + cseg * 8);
        #pragma unroll
        for (int i = 0; i < 2; ++i) {
            int j = tid + i * 256;
            int br = j >> 5;
            int bc = (j & 31) * 4;
            int col = n0 + bc;
            const uint32_t* src = Bp + (size_t)br * ldb + (col < N ? col : 0);
            uint32_t saddr = (uint32_t)__cvta_generic_to_shared(&Bs[0][br][bc]);
            int sz = (col < N) ? 16 : 0;
            asm volatile("cp.async.cg.shared.global [%0], [%1], 16, %2;\n"
                         :: "r"(saddr), "l"(src), "r"(sz));
        }
        asm volatile("cp.async.commit_group;\n");
        Af[ab1 + 0]  = areg0.x; Af[ab1 + 4]  = areg0.y;
        Af[ab1 + 8]  = areg0.z; Af[ab1 + 12] = areg0.w;
        Af[ab2 + 0]  = areg1.x; Af[ab2 + 4]  = areg1.y;
        Af[ab2 + 8]  = areg1.z; Af[ab2 + 12] = areg1.w;
    }

    for (int cc = 0; cc < chunks; ++cc) {
        const int st = cc & 1;
        if (cc + 1 < chunks) {
            const int k0 = (cc + 1) * 32;
            const int kp0 = (cc + 1) * 16;
            #pragma unroll
            for (int i = 0; i < 2; ++i) {
                int j = tid + i * 256;
                int br = j >> 5;
                int bc = (j & 31) * 4;
                int col = n0 + bc;
                const uint32_t* src = Bp + (size_t)(kp0 + br) * ldb + (col < N ? col : 0);
                uint32_t saddr = (uint32_t)__cvta_generic_to_shared(&Bs[st ^ 1][br][bc]);
                int sz = (col < N) ? 16 : 0;
                asm volatile("cp.async.cg.shared.global [%0], [%1], 16, %2;\n"
                             :: "r"(saddr), "l"(src), "r"(sz));
            }
            areg0 = *reinterpret_cast<const uint4*>(A + (size_t)(m0 + r)  * lda + k0 + cseg * 8);
            areg1 = *reinterpret_cast<const uint4*>(A + (size_t)(m0 + r2) * lda + k0 + cseg * 8);
        }
        asm volatile("cp.async.commit_group;\n");
        asm volatile("cp.async.wait_group 1;\n");
        __syncthreads();

        // wm selects 2 of the 8 m-tiles: mt = wm*2 + mi
        #pragma unroll
        for (int ks = 0; ks < 2; ++ks) {
            uint32_t af[2][4];
            #pragma unroll
            for (int mi = 0; mi < 2; ++mi) {
                int mt = wm * 2 + mi;
                uint4 a = *reinterpret_cast<const uint4*>(
                    &Af[(((mt * 2 + ks) << 5) + lane) << 2]);
                af[mi][0] = a.x; af[mi][1] = a.y; af[mi][2] = a.z; af[mi][3] = a.w;
            }
            #pragma unroll
            for (int ni = 0; ni < 8; ++ni) {
                int cB = wn * 64 + ni * 8 + g;
                uint32_t b0 = Bs[st][ks * 8 + t][cB];
                uint32_t b1 = Bs[st][ks * 8 + t + 4][cB];
                #pragma unroll
                for (int mi = 0; mi < 2; ++mi) {
                    asm volatile(
                        "mma.sync.aligned.m16n8k16.row.col.f32.f16.f16.f32 "
                        "{%0,%1,%2,%3}, {%4,%5,%6,%7}, {%8,%9}, {%0,%1,%2,%3};"
                        : "+f"(acc[mi][ni][0]), "+f"(acc[mi][ni][1]),
                          "+f"(acc[mi][ni][2]), "+f"(acc[mi][ni][3])
                        : "r"(af[mi][0]), "r"(af[mi][1]),
                          "r"(af[mi][2]), "r"(af[mi][3]),
                          "r"(b0), "r"(b1));
                }
            }
        }
        __syncthreads();
        if (cc + 1 < chunks) {
            Af[ab1 + 0]  = areg0.x; Af[ab1 + 4]  = areg0.y;
            Af[ab1 + 8]  = areg0.z; Af[ab1 + 12] = areg0.w;
            Af[ab2 + 0]  = areg1.x; Af[ab2 + 4]  = areg1.y;
            Af[ab2 + 8]  = areg1.z; Af[ab2 + 12] = areg1.w;
        }
    }

    #pragma unroll
    for (int mi = 0; mi < 2; ++mi) {
        int rr = wm * 32 + mi * 16 + g;        // local row (and +8)
        int r0 = m0 + rr;
        #pragma unroll
        for (int ni = 0; ni < 8; ++ni) {
            int col = n0 + wn * 64 + ni * 8 + 2 * t;
            if (col >= N) continue;
            float bv0 = bias[col], bv1 = bias[col + 1];
            if (MODE == 3) {
                *reinterpret_cast<__half2*>(&Ch[(size_t)r0 * ldch + col]) =
                    __floats2half2_rn(acc[mi][ni][0] + bv0, acc[mi][ni][1] + bv1);
                *reinterpret_cast<__half2*>(&Ch[(size_t)(r0 + 8) * ldch + col]) =
                    __floats2half2_rn(acc[mi][ni][2] + bv0, acc[mi][ni][3] + bv1);
            } else {  // MODE 6
                size_t o0 = (size_t)(r0 & 63) * ((size_t)TSTEPS * VOC)
                          + (size_t)(r0 >> 6) * VOC + col;
                size_t o1 = (size_t)((r0 + 8) & 63) * ((size_t)TSTEPS * VOC)
                          + (size_t)((r0 + 8) >> 6) * VOC + col;
                *reinterpret_cast<float2*>(&C[o0]) =
                    make_float2(acc[mi][ni][0] + bv0, acc[mi][ni][1] + bv1);
                *reinterpret_cast<float2*>(&C[o1]) =
                    make_float2(acc[mi][ni][2] + bv0, acc[mi][ni][3] + bv1);
            }
        }
    }
}

// ---------------- scores: grid (4, B), 256 threads, f16x2 tanh ----------------
__global__ void __launch_bounds__(256)
scores_kernel(const __half* __restrict__ uhsH,
              const float* __restrict__ wah,     // includes Wb bias
              const float* __restrict__ Aw,
              const float* __restrict__ Ab,
              const int* __restrict__ captions,
              const float* __restrict__ emb,
              const float* __restrict__ bcat,
              const __half* __restrict__ hrH,
              __half* __restrict__ incatH,
              float* __restrict__ gates,
              float* __restrict__ scores,
              int t) {
    const int q = blockIdx.x;
    const int b = blockIdx.y;
    const int tid = threadIdx.x;
    const int warp = tid >> 5;
    const int lane = tid & 31;

    __shared__ __align__(16) uint32_t s_wah2[ATT / 2];   // half2 pairs
    __shared__ __align__(16) float s_Aw[ATT];

    for (int i = tid; i < ATT / 2; i += 256) {
        float2 w = *reinterpret_cast<const float2*>(&wah[b * ATT + 2 * i]);
        s_wah2[i] = h2u(__floats2half2_rn(w.x, w.y));
    }
    for (int i = tid; i < ATT; i += 256) s_Aw[i] = Aw[i];
    __syncthreads();

    {
        int tok = captions[b * (TSTEPS + 1) + t];
        if (tid < 128) {
            int iq = q * 128 + tid;
            incatH[(size_t)b * KCAT + iq] = __float2half_rn(emb[(size_t)tok * EMB + iq]);
            incatH[(size_t)b * KCAT + EMB + ENC + iq] = hrH[b * DEC + iq];
        }
        int i0 = q * 512 + tid;
        gates[(size_t)b * GATES4 + i0]       = bcat[i0];
        gates[(size_t)b * GATES4 + i0 + 256] = bcat[i0 + 256];
    }

    const float Ab0 = Ab[0];
    const int f0 = q * 49;
    for (int f = f0 + warp; f < f0 + 49; f += 8) {
        const __half* u = uhsH + ((size_t)(b * NF + f)) * ATT;
        float a0 = 0.f, a1 = 0.f, a2 = 0.f, a3 = 0.f;
        #pragma unroll
        for (int kk = 0; kk < 4; ++kk) {
            int k = kk * 128 + lane * 4;
            uint2 uv = *reinterpret_cast<const uint2*>(u + k);
            uint32_t t01 = htanh2(hadd2u(uv.x, s_wah2[k >> 1]));
            uint32_t t23 = htanh2(hadd2u(uv.y, s_wah2[(k >> 1) + 1]));
            float2 f01 = u2f2(t01);
            float2 f23 = u2f2(t23);
            float4 av = *reinterpret_cast<const float4*>(&s_Aw[k]);
            a0 += f01.x * av.x;
            a1 += f01.y * av.y;
            a2 += f23.x * av.z;
            a3 += f23.y * av.w;
        }
        float acc = (a0 + a1) + (a2 + a3);
        #pragma unroll
        for (int o = 16; o; o >>= 1) acc += __shfl_xor_sync(0xffffffffu, acc, o);
        if (lane == 0) scores[b * NF + f] = acc + Ab0;
    }
}

// ---------------- ctx: softmax + context slice, grid (4, B), 512 threads ----
__global__ void __launch_bounds__(512)
ctx_kernel(const float* __restrict__ scores,
           const __half* __restrict__ featH,
           __half* __restrict__ incatH,
           float* __restrict__ alpha_out) {
    const int y = blockIdx.x;
    const int b = blockIdx.y;
    const int tid = threadIdx.x;
    const int warp = tid >> 5;
    const int lane = tid & 31;

    __shared__ float s_al[NF];
    __shared__ float s_red[16];
    __shared__ __align__(16) float4 s_part[4][128];

    float v = (tid < NF) ? scores[b * NF + tid] : -1e30f;
    float m = v;
    #pragma unroll
    for (int o = 16; o; o >>= 1) m = fmaxf(m, __shfl_xor_sync(0xffffffffu, m, o));
    if (lane == 0) s_red[warp] = m;
    __syncthreads();
    if (tid == 0) {
        float mm = s_red[0];
        #pragma unroll
        for (int w = 1; w < 16; ++w) mm = fmaxf(mm, s_red[w]);
        s_red[0] = mm;
    }
    __syncthreads();
    const float mx = s_red[0];
    __syncthreads();
    float e = (tid < NF) ? expf(v - mx) : 0.f;
    float s = e;
    #pragma unroll
    for (int o = 16; o; o >>= 1) s += __shfl_xor_sync(0xffffffffu, s, o);
    if (lane == 0) s_red[warp] = s;
    __syncthreads();
    if (tid == 0) {
        float ss = 0.f;
        #pragma unroll
        for (int w = 0; w < 16; ++w) ss += s_red[w];
        s_red[0] = ss;
    }
    __syncthreads();
    const float inv_denom = 1.0f / s_red[0];
    if (tid < NF) {
        float alpha = e * inv_denom;
        s_al[tid] = alpha;
        if (y == 0)
            alpha_out[(size_t)b * (TSTEPS * NF) + tid] = alpha;
    }
    __syncthreads();

    const int sub = tid >> 7;
    const int c4  = tid & 127;
    const int col = y * 512 + c4 * 4;
    const __half* fp = featH + (size_t)b * NF * ENC + col;
    float cx = 0.f, cy = 0.f, cz = 0.f, cw = 0.f;
    const int fs = sub * 49;
    #pragma unroll 7
    for (int f = fs; f < fs + 49; ++f) {
        uint2 fv = *reinterpret_cast<const uint2*>(fp + (size_t)f * ENC);
        float2 lo = u2f2(fv.x);
        float2 hi = u2f2(fv.y);
        float a = s_al[f];
        cx += a * lo.x; cy += a * lo.y; cz += a * hi.x; cw += a * hi.y;
    }
    s_part[sub][c4] = make_float4(cx, cy, cz, cw);
    __syncthreads();
    if (tid < 128) {
        float4 p0 = s_part[0][tid], p1 = s_part[1][tid];
        float4 p2 = s_part[2][tid], p3 = s_part[3][tid];
        uint2 o;
        o.x = h2u(__floats2half2_rn(p0.x + p1.x + p2.x + p3.x,
                                    p0.y + p1.y + p2.y + p3.y));
        o.y = h2u(__floats2half2_rn(p0.z + p1.z + p2.z + p3.z,
                                    p0.w + p1.w + p2.w + p3.w));
        *reinterpret_cast<uint2*>(
            &incatH[(size_t)b * KCAT + EMB + y * 512 + tid * 4]) = o;
    }
}

// ---------------- LSTM pointwise + wah bias-init ----------------
__global__ void lstm_kernel(const float* __restrict__ gates,
                            __half* __restrict__ hrH,
                            float* __restrict__ c,
                            float* __restrict__ wah,
                            const float* __restrict__ Wb) {
    int idx = blockIdx.x * blockDim.x + threadIdx.x;
    if (idx >= B * DEC) return;
    int b = idx / DEC;
    int n = idx - b * DEC;
    const float* g = gates + (size_t)b * GATES4;
    float i_ = g[n];
    float f_ = g[DEC + n];
    float gg = g[2 * DEC + n];
    float o_ = g[3 * DEC + n];
    float cc = c[idx];
    cc = sigmoidf_(f_) * cc + sigmoidf_(i_) * tanhf(gg);
    c[idx] = cc;
    hrH[idx] = __float2half_rn(sigmoidf_(o_) * tanhf(cc));
    wah[idx] = Wb[idx & (ATT - 1)];
}

// ---------------- launch ----------------
extern "C" void kernel_launch(void* const* d_in, const int* in_sizes, int n_in,
                              void* d_out, int out_size) {
    const float* features = (const float*)d_in[0];
    const int*   captions = (const int*)  d_in[1];
    const float* emb      = (const float*)d_in[2];
    const float* Uw       = (const float*)d_in[3];
    const float* Ub       = (const float*)d_in[4];
    const float* Ww       = (const float*)d_in[5];
    const float* Wb       = (const float*)d_in[6];
    const float* Aw       = (const float*)d_in[7];
    const float* Ab       = (const float*)d_in[8];
    const float* ih_w     = (const float*)d_in[9];
    const float* ih_b     = (const float*)d_in[10];
    const float* ic_w     = (const float*)d_in[11];
    const float* ic_b     = (const float*)d_in[12];
    const float* W_ih     = (const float*)d_in[13];
    const float* b_ih     = (const float*)d_in[14];
    const float* W_hh     = (const float*)d_in[15];
    const float* b_hh     = (const float*)d_in[16];
    const float* fcn_w    = (const float*)d_in[17];
    const float* fcn_b    = (const float*)d_in[18];
    float* out = (float*)d_out;

    float* S = nullptr;
    cudaGetSymbolAddress((void**)&S, g_scratch);
    __half*   uhsH   = reinterpret_cast<__half*>(S + OFF_UHSH);
    uint32_t* WcatP  = reinterpret_cast<uint32_t*>(S + OFF_WCATP);
    uint32_t* FcnP   = reinterpret_cast<uint32_t*>(S + OFF_FCNP);
    uint32_t* WwP    = reinterpret_cast<uint32_t*>(S + OFF_WWP);
    uint32_t* ihP    = reinterpret_cast<uint32_t*>(S + OFF_IHP);
    uint32_t* icP    = reinterpret_cast<uint32_t*>(S + OFF_ICP);
    uint32_t* UwP    = reinterpret_cast<uint32_t*>(S + OFF_UWP);
    __half*   featH  = reinterpret_cast<__half*>(S + OFF_FEATH);
    __half*   meanfH = reinterpret_cast<__half*>(S + OFF_MEANFH);
    float*    c      = S + OFF_CB;
    __half*   hrAll  = reinterpret_cast<__half*>(S + OFF_HRALL);
    float*    wah    = S + OFF_WAH;
    __half*   incatH = reinterpret_cast<__half*>(S + OFF_INCATH);
    float*    gates  = S + OFF_GATES;
    float*    bcat   = S + OFF_BCAT;
    float*    sc     = S + OFF_SC;

    cudaStream_t s2;
    cudaStreamCreateWithFlags(&s2, cudaStreamNonBlocking);
    cudaEvent_t start_ev, feat_ev, pjoin_ev;
    cudaEventCreateWithFlags(&start_ev, cudaEventDisableTiming);
    cudaEventCreateWithFlags(&feat_ev, cudaEventDisableTiming);
    cudaEventCreateWithFlags(&pjoin_ev, cudaEventDisableTiming);

    cudaEventRecord(start_ev, 0);
    cudaStreamWaitEvent(s2, start_ev, 0);

    // ---- prep, parallel across 2 streams; uhs GEMM is the 4th launch ----
    prep_wcat_kernel<<<2048, 256, 0, s2>>>(W_ih, W_hh, b_ih, b_hh, WcatP, bcat); // 1
    feat2h_kernel<<<(B * NF * ENC / 4 + 255) / 256, 256>>>(                      // 2
        features, featH, B * NF * ENC / 4);
    cudaEventRecord(feat_ev, 0);
    pack_weight_kernel<<<512, 256>>>(Uw, UwP, ENC, ATT);                         // 3
    h16_gemm128<3><<<dim3(ATT / 128, (B * NF) / 128, 1), 256>>>(featH, ENC,      // 4 <- ncu
        UwP, ATT, nullptr, Ub, uhsH, ATT, B * NF, ATT, ENC);
    // s2: remaining packs + h0/c0/wah0 chain
    pack_weight_kernel<<<512, 256, 0, s2>>>(ih_w, ihP, ENC, DEC);
    pack_weight_kernel<<<512, 256, 0, s2>>>(ic_w, icP, ENC, DEC);
    pack_weight_kernel<<<256, 256, 0, s2>>>(Ww, WwP, DEC, ATT);
    pack_weight_kernel<<<2048, 256, 0, s2>>>(fcn_w, FcnP, DEC, VOC);
    cudaStreamWaitEvent(s2, feat_ev, 0);
    meanf_h_kernel<<<(B * (ENC / 4) + 255) / 256, 256, 0, s2>>>(featH, meanfH);
    h16_gemm<3><<<dim3(DEC / 128, 1, 1), 256, 0, s2>>>(meanfH, ENC, ihP, DEC,
        nullptr, 0, ih_b, hrAll, DEC, B, DEC, ENC);                 // h0 -> hrAll[0]
    h16_gemm<1><<<dim3(DEC / 128, 1, 1), 256, 0, s2>>>(meanfH, ENC, icP, DEC,
        c, DEC, ic_b, nullptr, 0, B, DEC, ENC);
    h16_gemm<1><<<dim3(ATT / 128, 1, 1), 256, 0, s2>>>(hrAll, DEC, WwP, ATT,
        wah, ATT, Wb, nullptr, 0, B, ATT, DEC);                     // wah0 (+Wb)
    cudaEventRecord(pjoin_ev, s2);

    cudaStreamWaitEvent(0, pjoin_ev, 0);

    // ---- recurrent steps (single stream; preds deferred) ----
    for (int t = 0; t < TSTEPS; ++t) {
        float* alpha_t = out + ALPHA_OFF + (size_t)t * NF;
        __half* hr_in  = hrAll + (size_t)t * B * DEC;
        __half* hr_out = hrAll + (size_t)(t + 1) * B * DEC;

        scores_kernel<<<dim3(4, B), 256>>>(uhsH, wah, Aw, Ab, captions, emb,
                                           bcat, hr_in, incatH, gates, sc, t);
        ctx_kernel<<<dim3(4, B), 512>>>(sc, featH, incatH, alpha_t);
        h16_gemm<0><<<dim3(GATES4 / 128, 1, 8), 256>>>(incatH, KCAT, WcatP, GATES4,
            gates, GATES4, nullptr, nullptr, 0, B, GATES4, KCAT);
        lstm_kernel<<<(B * DEC + 255) / 256, 256>>>(gates, hr_out, c, wah, Wb);
        if (t + 1 < TSTEPS)
            h16_gemm<0><<<dim3(ATT / 128, 1, 4), 256>>>(hr_out, DEC, WwP, ATT,
                wah, ATT, nullptr, nullptr, 0, B, ATT, DEC);
    }

    // ---- batched preds: [all h_1..h_24] @ fcn_w + fcn_b, M = 1536 ----
    h16_gemm128<6><<<dim3((VOC + 127) / 128, (B * TSTEPS) / 128, 1), 256>>>(
        hrAll + (size_t)B * DEC, DEC, FcnP, VOC,
        out, fcn_b, nullptr, 0, B * TSTEPS, VOC, DEC);
}